// round 3
// baseline (speedup 1.0000x reference)
#include <cuda_runtime.h>
#include <cstdint>

// Problem constants
#define NB    4
#define TPTS  65536
#define RG    32
#define GV    32768          // 32^3 voxels
#define HD    128
#define PT    64             // points per tile
#define XP    65             // padded pitch for transposed activations in smem

// ---------------- scratch (no cudaMalloc allowed) ----------------
__device__ float g_net[33554432];    // [4][65536][128]
__device__ int   g_index[262144];    // [4][65536]
__device__ float g_grid[16777216];   // [4][32768][128]  (max-pool / sums)
__device__ float g_cnt[131072];      // [4][32768]

// ---------------- helpers ----------------
__device__ __forceinline__ void fma4(float4& a, float s, float4 w) {
    a.x = fmaf(s, w.x, a.x);
    a.y = fmaf(s, w.y, a.y);
    a.z = fmaf(s, w.z, a.z);
    a.w = fmaf(s, w.w, a.w);
}

// float atomic max via sign-split: positives (incl +0) -> signed atomicMax,
// negatives (incl -0) -> unsigned atomicMin. Init pattern 0xFFFFFFFF works for both paths.
__device__ __forceinline__ void atomic_max_f(float* a, float v) {
    unsigned int uv = __float_as_uint(v);
    if (uv >> 31) atomicMin((unsigned int*)a, uv);
    else          atomicMax((int*)a, (int)uv);
}

// dual GEMM over K=256: accH += relu(x)@W0 , accS += x@Ws
// xT: [256][XP] transposed activations in smem. wbuf: 2*64*128 floats smem staging.
__device__ __forceinline__ void mm_dual256(
    const float* __restrict__ xT, const float* __restrict__ w0g,
    const float* __restrict__ wsg, float* wbuf,
    float4 accH[8], float4 accS[8], int tc, int tp, int tid)
{
    float4* w0c = (float4*)wbuf;
    float4* wsc = (float4*)(wbuf + 64 * 128);
    for (int kc = 0; kc < 256; kc += 64) {
        __syncthreads();
        const float4* w0s = (const float4*)(w0g + kc * 128);
        const float4* wss = (const float4*)(wsg + kc * 128);
#pragma unroll
        for (int l = 0; l < 8; l++) {
            int fi = tid + l * 256;          // 0..2047 float4s (64x128)
            w0c[fi] = w0s[fi];
            wsc[fi] = wss[fi];
        }
        __syncthreads();
#pragma unroll 4
        for (int kk = 0; kk < 64; kk++) {
            const float* xrow = xT + (kc + kk) * XP + 8 * tp;  // broadcast reads
            float4 w0v = w0c[kk * 32 + tc];
            float4 wsv = wsc[kk * 32 + tc];
#pragma unroll
            for (int p = 0; p < 8; p++) {
                float xs = xrow[p];
                float xr = fmaxf(xs, 0.0f);
                fma4(accH[p], xr, w0v);
                fma4(accS[p], xs, wsv);
            }
        }
    }
}

// single GEMM: acc += xT@W   (KIN = 128 here), wbuf: 64*128 floats smem staging
template <int KIN>
__device__ __forceinline__ void mm_single(
    const float* __restrict__ xT, const float* __restrict__ wg, float* wbuf,
    float4 acc[8], int tc, int tp, int tid)
{
    float4* wc = (float4*)wbuf;
    for (int kc = 0; kc < KIN; kc += 64) {
        __syncthreads();
        const float4* ws = (const float4*)(wg + kc * 128);
#pragma unroll
        for (int l = 0; l < 8; l++) wc[tid + l * 256] = ws[tid + l * 256];
        __syncthreads();
#pragma unroll 4
        for (int kk = 0; kk < 64; kk++) {
            const float* xrow = xT + (kc + kk) * XP + 8 * tp;
            float4 wv = wc[kk * 32 + tc];
#pragma unroll
            for (int p = 0; p < 8; p++) fma4(acc[p], xrow[p], wv);
        }
    }
}

// shared epilogue for resblock: h = relu(accH + b0) -> hT; accS += relu(h)@W1; out = accS + b1
__device__ __forceinline__ void resblock_tail(
    float* hT, float* wbuf,
    const float* __restrict__ b0g, const float* __restrict__ w1g,
    const float* __restrict__ b1g,
    float4 accH[8], float4 accS[8], int tc, int tp, int tid, int pt0)
{
    float4 b0v = *(const float4*)(b0g + 4 * tc);
#pragma unroll
    for (int p = 0; p < 8; p++) {
        int pp = 8 * tp + p;
        hT[(4 * tc + 0) * XP + pp] = fmaxf(accH[p].x + b0v.x, 0.0f);
        hT[(4 * tc + 1) * XP + pp] = fmaxf(accH[p].y + b0v.y, 0.0f);
        hT[(4 * tc + 2) * XP + pp] = fmaxf(accH[p].z + b0v.z, 0.0f);
        hT[(4 * tc + 3) * XP + pp] = fmaxf(accH[p].w + b0v.w, 0.0f);
    }
    mm_single<128>(hT, w1g, wbuf, accS, tc, tp, tid);  // internal sync covers hT stores
    float4 b1v = *(const float4*)(b1g + 4 * tc);
#pragma unroll
    for (int p = 0; p < 8; p++) {
        float4 o = accS[p];
        o.x += b1v.x; o.y += b1v.y; o.z += b1v.z; o.w += b1v.w;
        *((float4*)&g_net[(size_t)(pt0 + 8 * tp + p) * HD + 4 * tc]) = o;
    }
}

// ---------------- kernel 1: index + pos-enc + fc_pos + resblock0 ----------------
__global__ __launch_bounds__(256, 1) void input_kernel(
    const float* __restrict__ pg,
    const float* __restrict__ fcpw, const float* __restrict__ fcpb,
    const float* __restrict__ w0g, const float* __restrict__ b0g,
    const float* __restrict__ w1g, const float* __restrict__ b1g,
    const float* __restrict__ wsg)
{
    extern __shared__ float sm[];
    float* xT     = sm;                       // 256*XP
    float* region = sm + 256 * XP;
    float* peT    = region;                   // 60*XP
    float* fcw    = region + 60 * XP;         // 60*256
    float* wbuf   = region;                   // phase2: 2*64*128
    float* hT     = region + 2 * 64 * 128;    // 128*XP

    int tid = threadIdx.x;
    int pt0 = blockIdx.x * PT;

    // grid index per point
    if (tid < PT) {
        int pt = pt0 + tid;
        float px = pg[pt * 3 + 0], py = pg[pt * 3 + 1], pz = pg[pt * 3 + 2];
        const float hi = 1.0f - 1e-3f;
        float nx = fminf(fmaxf(px / 1.101f + 0.5f, 0.0f), hi);
        float ny = fminf(fmaxf(py / 1.101f + 0.5f, 0.0f), hi);
        float nz = fminf(fmaxf(pz / 1.101f + 0.5f, 0.0f), hi);
        int xi = (int)(nx * 32.0f), yi = (int)(ny * 32.0f), zi = (int)(nz * 32.0f);
        g_index[pt] = xi + 32 * (yi + 32 * zi);
    }

    // positional encoding -> peT[60][XP]
#pragma unroll
    for (int l = 0; l < 8; l++) {
        int task = tid + l * 256;
        if (task < PT * 30) {
            int pi = task / 30, j = task % 30;
            int fr = j / 3, coord = j % 3;
            float pv = pg[(pt0 + pi) * 3 + coord];
            float f = exp2f((float)fr) * 3.14159265358979323846f;
            float s, c;
            sincosf(f * pv, &s, &c);
            peT[(fr * 6 + coord) * XP + pi]     = s;
            peT[(fr * 6 + 3 + coord) * XP + pi] = c;
        }
    }
    // stage fc_pos_w (60x256)
    {
        float4* d = (float4*)fcw;
        const float4* s4 = (const float4*)fcpw;
#pragma unroll
        for (int l = 0; l < 15; l++) d[tid + l * 256] = s4[tid + l * 256];
    }
    __syncthreads();

    // fc_pos GEMM: [64 pts x 60] @ [60 x 256] -> xT[256][XP]
    {
        int tc6 = tid & 63, tpg = tid >> 6;      // 64 ch-groups x 4 pt-groups(16 pts)
        float4 acc[16];
#pragma unroll
        for (int p = 0; p < 16; p++) acc[p] = make_float4(0.f, 0.f, 0.f, 0.f);
        for (int k = 0; k < 60; k++) {
            float4 wv = ((float4*)fcw)[k * 64 + tc6];
            const float* xr = peT + k * XP + 16 * tpg;
#pragma unroll
            for (int p = 0; p < 16; p++) fma4(acc[p], xr[p], wv);
        }
        float4 bv = *(const float4*)(fcpb + 4 * tc6);
#pragma unroll
        for (int p = 0; p < 16; p++) {
            int pp = 16 * tpg + p;
            xT[(4 * tc6 + 0) * XP + pp] = acc[p].x + bv.x;
            xT[(4 * tc6 + 1) * XP + pp] = acc[p].y + bv.y;
            xT[(4 * tc6 + 2) * XP + pp] = acc[p].z + bv.z;
            xT[(4 * tc6 + 3) * XP + pp] = acc[p].w + bv.w;
        }
    }

    // resblock 0
    int tc = tid & 31, tp = tid >> 5;
    float4 accH[8], accS[8];
#pragma unroll
    for (int p = 0; p < 8; p++) { accH[p] = make_float4(0.f,0.f,0.f,0.f); accS[p] = accH[p]; }
    mm_dual256(xT, w0g, wsg, wbuf, accH, accS, tc, tp, tid);  // first sync covers xT writes
    resblock_tail(hT, wbuf, b0g, w1g, b1g, accH, accS, tc, tp, tid, pt0);
}

// ---------------- resblock i (with pooled-feature gather) ----------------
__global__ __launch_bounds__(256, 1) void resblock_kernel(
    const float* __restrict__ w0g, const float* __restrict__ b0g,
    const float* __restrict__ w1g, const float* __restrict__ b1g,
    const float* __restrict__ wsg)
{
    extern __shared__ float sm[];
    float* xT   = sm;                        // 256*XP
    float* wbuf = sm + 256 * XP;             // 2*64*128
    float* hT   = wbuf + 2 * 64 * 128;       // 128*XP
    int*   idx_s = (int*)(hT + 128 * XP);    // 64

    int tid = threadIdx.x;
    int tc = tid & 31, tp = tid >> 5;
    int pt0 = blockIdx.x * PT;
    int b = pt0 >> 16;   // / TPTS

    if (tid < PT) idx_s[tid] = g_index[pt0 + tid];
    __syncthreads();

    // x = concat(net, pooled) -> transposed smem
    const float4* net4 = (const float4*)&g_net[(size_t)pt0 * HD];
#pragma unroll
    for (int l = 0; l < 16; l++) {
        int fi = tid + l * 256;      // 0..4095
        int p = fi >> 6, q = fi & 63;
        float4 v;
        if (q < 32) v = net4[p * 32 + q];
        else        v = *(((const float4*)&g_grid[(size_t)(b * GV + idx_s[p]) * HD]) + (q - 32));
        int k0 = 4 * q;
        xT[(k0 + 0) * XP + p] = v.x;
        xT[(k0 + 1) * XP + p] = v.y;
        xT[(k0 + 2) * XP + p] = v.z;
        xT[(k0 + 3) * XP + p] = v.w;
    }

    float4 accH[8], accS[8];
#pragma unroll
    for (int p = 0; p < 8; p++) { accH[p] = make_float4(0.f,0.f,0.f,0.f); accS[p] = accH[p]; }
    mm_dual256(xT, w0g, wsg, wbuf, accH, accS, tc, tp, tid);
    resblock_tail(hT, wbuf, b0g, w1g, b1g, accH, accS, tc, tp, tid, pt0);
}

// ---------------- scatter max pool: net -> grid ----------------
__global__ __launch_bounds__(256) void scatter_max_kernel()
{
    int gw = (blockIdx.x * 256 + threadIdx.x) >> 5;   // point id
    int lane = threadIdx.x & 31;
    int b = gw >> 16;
    int v = g_index[gw];
    float4 val = *(((const float4*)&g_net[(size_t)gw * HD]) + lane);
    float* dst = &g_grid[(size_t)(b * GV + v) * HD + 4 * lane];
    atomic_max_f(dst + 0, val.x);
    atomic_max_f(dst + 1, val.y);
    atomic_max_f(dst + 2, val.z);
    atomic_max_f(dst + 3, val.w);
}

// ---------------- final fc_c + scatter add ----------------
__global__ __launch_bounds__(256, 1) void final_kernel(
    const float* __restrict__ wcg, const float* __restrict__ bcg)
{
    extern __shared__ float sm[];
    float* xT   = sm;                    // 128*XP
    float* wbuf = sm + 128 * XP;         // 64*128
    int*   idx_s = (int*)(wbuf + 64 * 128);

    int tid = threadIdx.x;
    int tc = tid & 31, tp = tid >> 5;
    int pt0 = blockIdx.x * PT;
    int b = pt0 >> 16;

    if (tid < PT) idx_s[tid] = g_index[pt0 + tid];

    const float4* net4 = (const float4*)&g_net[(size_t)pt0 * HD];
#pragma unroll
    for (int l = 0; l < 8; l++) {
        int fi = tid + l * 256;      // 0..2047
        int p = fi >> 5, q = fi & 31;
        float4 v = net4[p * 32 + q];
        int k0 = 4 * q;
        xT[(k0 + 0) * XP + p] = v.x;
        xT[(k0 + 1) * XP + p] = v.y;
        xT[(k0 + 2) * XP + p] = v.z;
        xT[(k0 + 3) * XP + p] = v.w;
    }

    float4 acc[8];
#pragma unroll
    for (int p = 0; p < 8; p++) acc[p] = make_float4(0.f, 0.f, 0.f, 0.f);
    mm_single<128>(xT, wcg, wbuf, acc, tc, tp, tid);   // sync covers xT & idx_s

    float4 bv = *(const float4*)(bcg + 4 * tc);
#pragma unroll
    for (int p = 0; p < 8; p++) {
        int pp = 8 * tp + p;
        float* dst = &g_grid[(size_t)(b * GV + idx_s[pp]) * HD + 4 * tc];
        atomicAdd(dst + 0, acc[p].x + bv.x);
        atomicAdd(dst + 1, acc[p].y + bv.y);
        atomicAdd(dst + 2, acc[p].z + bv.z);
        atomicAdd(dst + 3, acc[p].w + bv.w);
    }
    if (tid < PT) atomicAdd(&g_cnt[b * GV + idx_s[tid]], 1.0f);
}

// ---------------- finalize: mean + transpose to [B,C,32,32,32] ----------------
__global__ __launch_bounds__(256) void finalize_kernel(float* __restrict__ out)
{
    __shared__ float s[32 * 129];
    __shared__ float inv[32];
    int tid = threadIdx.x;
    int blk = blockIdx.x;             // 0..4095
    int b = blk >> 10;
    int v0 = (blk & 1023) * 32;

    const float4* src = (const float4*)&g_grid[(size_t)(b * GV + v0) * HD];
#pragma unroll
    for (int l = 0; l < 4; l++) {
        int fi = tid + l * 256;       // 0..1023 float4 loads (32 voxels x 32 float4)
        int vv = fi >> 5, q = fi & 31;
        float4 x = src[vv * 32 + q];
        s[vv * 129 + 4 * q + 0] = x.x;
        s[vv * 129 + 4 * q + 1] = x.y;
        s[vv * 129 + 4 * q + 2] = x.z;
        s[vv * 129 + 4 * q + 3] = x.w;
    }
    if (tid < 32) inv[tid] = 1.0f / fmaxf(g_cnt[b * GV + v0 + tid], 1.0f);
    __syncthreads();

    float* ob = out + (size_t)b * HD * GV + v0;
#pragma unroll
    for (int l = 0; l < 16; l++) {
        int oi = tid + l * 256;       // 0..4095 outputs (128 ch x 32 voxels)
        int ch = oi >> 5, vv = oi & 31;
        ob[(size_t)ch * GV + vv] = s[vv * 129 + ch] * inv[vv];
    }
}

// ---------------- fills ----------------
__global__ void fill_grid_kernel(unsigned int val)
{
    int i = blockIdx.x * 256 + threadIdx.x;   // uint4 index; total 4194304
    ((uint4*)g_grid)[i] = make_uint4(val, val, val, val);
}
__global__ void fill_cnt_kernel()
{
    int i = blockIdx.x * 256 + threadIdx.x;
    if (i < NB * GV) g_cnt[i] = 0.0f;
}

// ---------------- host ----------------
extern "C" void kernel_launch(void* const* d_in, const int* in_sizes, int n_in,
                              void* d_out, int out_size)
{
    const float* p        = (const float*)d_in[0];
    const float* fc_pos_w = (const float*)d_in[1];
    const float* fc_pos_b = (const float*)d_in[2];
    const float* fc0_w    = (const float*)d_in[3];
    const float* fc0_b    = (const float*)d_in[4];
    const float* fc1_w    = (const float*)d_in[5];
    const float* fc1_b    = (const float*)d_in[6];
    const float* sc_w     = (const float*)d_in[7];
    const float* fc_c_w   = (const float*)d_in[8];
    const float* fc_c_b   = (const float*)d_in[9];
    float* out = (float*)d_out;

    const int SMEM_K1 = (256 * XP + 2 * 64 * 128 + 128 * XP) * 4;          // 165376
    const int SMEM_RB = SMEM_K1 + 256;                                     // + idx_s
    const int SMEM_FC = (128 * XP + 64 * 128) * 4 + 256;                   // 66304

    cudaFuncSetAttribute(input_kernel,    cudaFuncAttributeMaxDynamicSharedMemorySize, SMEM_K1);
    cudaFuncSetAttribute(resblock_kernel, cudaFuncAttributeMaxDynamicSharedMemorySize, SMEM_RB);
    cudaFuncSetAttribute(final_kernel,    cudaFuncAttributeMaxDynamicSharedMemorySize, SMEM_FC);

    const int NTILES = NB * TPTS / PT;    // 4096

    input_kernel<<<NTILES, 256, SMEM_K1>>>(p, fc_pos_w, fc_pos_b,
                                           fc0_w, fc0_b, fc1_w, fc1_b, sc_w);

    for (int i = 1; i < 5; i++) {
        fill_grid_kernel<<<16384, 256>>>(0xFFFFFFFFu);
        scatter_max_kernel<<<NB * TPTS / 8, 256>>>();
        resblock_kernel<<<NTILES, 256, SMEM_RB>>>(fc0_w + i * 256 * 128,
                                                  fc0_b + i * 128,
                                                  fc1_w + i * 128 * 128,
                                                  fc1_b + i * 128,
                                                  sc_w + i * 256 * 128);
    }

    fill_grid_kernel<<<16384, 256>>>(0u);
    fill_cnt_kernel<<<512, 256>>>();
    final_kernel<<<NTILES, 256, SMEM_FC>>>(fc_c_w, fc_c_b);
    finalize_kernel<<<NB * GV / 32, 256>>>(out);
}

// round 4
// speedup vs baseline: 1.1646x; 1.1646x over previous
#include <cuda_runtime.h>
#include <cstdint>

// Problem constants
#define NB    4
#define TPTS  65536
#define GV    32768          // 32^3 voxels
#define HD    128
#define PT    64             // points per tile

// point-major activation pitches (floats); multiples of 4 for float4 alignment
#define XPIT  264            // 256 ch + pad
#define XP4   66
#define HPIT  132            // 128 ch + pad
#define HP4   33

// ---------------- scratch (no cudaMalloc allowed) ----------------
__device__ float g_net[33554432];    // [4][65536][128]
__device__ int   g_index[262144];    // [4][65536]
__device__ float g_grid[16777216];   // [4][32768][128]  (max-pool / sums)
__device__ float g_cnt[131072];      // [4][32768]

// ---------------- helpers ----------------
__device__ __forceinline__ void fma4(float4& a, float s, float4 w) {
    a.x = fmaf(s, w.x, a.x);
    a.y = fmaf(s, w.y, a.y);
    a.z = fmaf(s, w.z, a.z);
    a.w = fmaf(s, w.w, a.w);
}

// float atomic max via sign-split.
__device__ __forceinline__ void atomic_max_f(float* a, float v) {
    unsigned int uv = __float_as_uint(v);
    if (uv >> 31) atomicMin((unsigned int*)a, uv);
    else          atomicMax((int*)a, (int)uv);
}

// dual GEMM over K=256: accH += relu(x)@W0 , accS += x@Ws
// xP point-major [64][XPIT]; wbuf = 2 * 32*128 floats (32-row chunks)
__device__ __forceinline__ void mm_dual256(
    const float* __restrict__ xP, const float* __restrict__ w0g,
    const float* __restrict__ wsg, float* wbuf,
    float4 accH[8], float4 accS[8], int tc, int tp, int tid)
{
    float4* w0c = (float4*)wbuf;
    float4* wsc = (float4*)(wbuf + 32 * 128);
    for (int kc = 0; kc < 256; kc += 32) {
        __syncthreads();
        const float4* w0s = (const float4*)(w0g + kc * 128);
        const float4* wss = (const float4*)(wsg + kc * 128);
#pragma unroll
        for (int l = 0; l < 4; l++) {
            int fi = tid + l * 256;          // 0..1023 float4 (32x128)
            w0c[fi] = w0s[fi];
            wsc[fi] = wss[fi];
        }
        __syncthreads();
#pragma unroll 2
        for (int s = 0; s < 8; s++) {        // 4 k per step
            float4 w00 = w0c[(4 * s + 0) * 32 + tc];
            float4 w01 = w0c[(4 * s + 1) * 32 + tc];
            float4 w02 = w0c[(4 * s + 2) * 32 + tc];
            float4 w03 = w0c[(4 * s + 3) * 32 + tc];
            float4 ws0 = wsc[(4 * s + 0) * 32 + tc];
            float4 ws1 = wsc[(4 * s + 1) * 32 + tc];
            float4 ws2 = wsc[(4 * s + 2) * 32 + tc];
            float4 ws3 = wsc[(4 * s + 3) * 32 + tc];
            const float* xb = xP + kc + 4 * s + (8 * tp) * XPIT;
#pragma unroll
            for (int p = 0; p < 8; p++) {
                float4 xv = *(const float4*)(xb + p * XPIT);   // broadcast
                fma4(accS[p], xv.x, ws0);
                fma4(accS[p], xv.y, ws1);
                fma4(accS[p], xv.z, ws2);
                fma4(accS[p], xv.w, ws3);
                float4 xr;
                xr.x = fmaxf(xv.x, 0.0f); xr.y = fmaxf(xv.y, 0.0f);
                xr.z = fmaxf(xv.z, 0.0f); xr.w = fmaxf(xv.w, 0.0f);
                fma4(accH[p], xr.x, w00);
                fma4(accH[p], xr.y, w01);
                fma4(accH[p], xr.z, w02);
                fma4(accH[p], xr.w, w03);
            }
        }
    }
}

// single GEMM: acc += xP@W ; xP point-major [64][PITCH], KIN cols; wbuf >= 32*128 floats
template <int KIN, int PITCH>
__device__ __forceinline__ void mm_single(
    const float* __restrict__ xP, const float* __restrict__ wg, float* wbuf,
    float4 acc[8], int tc, int tp, int tid)
{
    float4* wc = (float4*)wbuf;
    for (int kc = 0; kc < KIN; kc += 32) {
        __syncthreads();
        const float4* ws = (const float4*)(wg + kc * 128);
#pragma unroll
        for (int l = 0; l < 4; l++) wc[tid + l * 256] = ws[tid + l * 256];
        __syncthreads();
#pragma unroll 2
        for (int s = 0; s < 8; s++) {
            float4 w0 = wc[(4 * s + 0) * 32 + tc];
            float4 w1 = wc[(4 * s + 1) * 32 + tc];
            float4 w2 = wc[(4 * s + 2) * 32 + tc];
            float4 w3 = wc[(4 * s + 3) * 32 + tc];
            const float* xb = xP + kc + 4 * s + (8 * tp) * PITCH;
#pragma unroll
            for (int p = 0; p < 8; p++) {
                float4 xv = *(const float4*)(xb + p * PITCH);
                fma4(acc[p], xv.x, w0);
                fma4(acc[p], xv.y, w1);
                fma4(acc[p], xv.z, w2);
                fma4(acc[p], xv.w, w3);
            }
        }
    }
}

// resblock tail: h = relu(accH+b0) -> hP (overlaid on xP, so sync first);
// accS += h@W1; out = accS + b1 -> g_net
__device__ __forceinline__ void resblock_tail(
    float* hP, float* wbuf,
    const float* __restrict__ b0g, const float* __restrict__ w1g,
    const float* __restrict__ b1g,
    float4 accH[8], float4 accS[8], int tc, int tp, int tid, int pt0)
{
    __syncthreads();   // all xP reads done before hP overlay write
    float4 b0v = *(const float4*)(b0g + 4 * tc);
    float4* hP4 = (float4*)hP;
#pragma unroll
    for (int p = 0; p < 8; p++) {
        float4 h;
        h.x = fmaxf(accH[p].x + b0v.x, 0.0f);
        h.y = fmaxf(accH[p].y + b0v.y, 0.0f);
        h.z = fmaxf(accH[p].z + b0v.z, 0.0f);
        h.w = fmaxf(accH[p].w + b0v.w, 0.0f);
        hP4[(8 * tp + p) * HP4 + tc] = h;
    }
    mm_single<128, HPIT>(hP, w1g, wbuf, accS, tc, tp, tid);  // first sync orders hP
    float4 b1v = *(const float4*)(b1g + 4 * tc);
#pragma unroll
    for (int p = 0; p < 8; p++) {
        float4 o = accS[p];
        o.x += b1v.x; o.y += b1v.y; o.z += b1v.z; o.w += b1v.w;
        *((float4*)&g_net[(size_t)(pt0 + 8 * tp + p) * HD + 4 * tc]) = o;
    }
}

// ---------------- kernel 1: index + pos-enc + fc_pos + resblock0 ----------------
__global__ __launch_bounds__(256, 2) void input_kernel(
    const float* __restrict__ pg,
    const float* __restrict__ fcpw, const float* __restrict__ fcpb,
    const float* __restrict__ w0g, const float* __restrict__ b0g,
    const float* __restrict__ w1g, const float* __restrict__ b1g,
    const float* __restrict__ wsg)
{
    extern __shared__ float sm[];
    float* xP     = sm;                      // 64*264 = 16896 floats
    float* region = sm + 64 * XPIT;
    float* peP    = region;                  // 64*64 = 4096 floats
    float* fcwc   = region + 4096;           // 20*256 = 5120 floats
    float* wbuf   = region;                  // phase B: 2*32*128 = 8192 floats
    float* hP     = xP;                      // overlay

    int tid = threadIdx.x;
    int pt0 = blockIdx.x * PT;

    // grid index per point
    if (tid < PT) {
        int pt = pt0 + tid;
        float px = pg[pt * 3 + 0], py = pg[pt * 3 + 1], pz = pg[pt * 3 + 2];
        const float hi = 1.0f - 1e-3f;
        float nx = fminf(fmaxf(px / 1.101f + 0.5f, 0.0f), hi);
        float ny = fminf(fmaxf(py / 1.101f + 0.5f, 0.0f), hi);
        float nz = fminf(fmaxf(pz / 1.101f + 0.5f, 0.0f), hi);
        int xi = (int)(nx * 32.0f), yi = (int)(ny * 32.0f), zi = (int)(nz * 32.0f);
        g_index[pt] = xi + 32 * (yi + 32 * zi);
    }

    // positional encoding -> peP[64][64] point-major (rows of 60 used)
#pragma unroll
    for (int l = 0; l < 8; l++) {
        int task = tid + l * 256;
        if (task < PT * 30) {
            int pi = task / 30, j = task % 30;
            int fr = j / 3, coord = j % 3;
            float pv = pg[(pt0 + pi) * 3 + coord];
            float f = exp2f((float)fr) * 3.14159265358979323846f;
            float s, c;
            sincosf(f * pv, &s, &c);
            peP[pi * 64 + fr * 6 + coord]     = s;
            peP[pi * 64 + fr * 6 + 3 + coord] = c;
        }
    }

    // fc_pos GEMM: [64 x 60] @ [60 x 256] -> xP[64][256]
    {
        int tc6 = tid & 63, tpg = tid >> 6;    // 64 ch-groups x 4 pt-groups(16)
        float4 acc[16];
#pragma unroll
        for (int p = 0; p < 16; p++) acc[p] = make_float4(0.f, 0.f, 0.f, 0.f);
        for (int kc = 0; kc < 60; kc += 20) {
            __syncthreads();                   // first iter also orders peP writes
            const float4* ws = (const float4*)(fcpw + kc * 256);
#pragma unroll
            for (int l = 0; l < 5; l++) ((float4*)fcwc)[tid + l * 256] = ws[tid + l * 256];
            __syncthreads();
#pragma unroll 2
            for (int s = 0; s < 10; s++) {     // 2 k per step
                float4 w0 = ((float4*)fcwc)[(2 * s + 0) * 64 + tc6];
                float4 w1 = ((float4*)fcwc)[(2 * s + 1) * 64 + tc6];
                const float* xb = peP + (16 * tpg) * 64 + kc + 2 * s;
#pragma unroll
                for (int p = 0; p < 16; p++) {
                    float2 xv = *(const float2*)(xb + p * 64);
                    fma4(acc[p], xv.x, w0);
                    fma4(acc[p], xv.y, w1);
                }
            }
        }
        float4 bv = *(const float4*)(fcpb + 4 * tc6);
        float4* xP4 = (float4*)xP;
#pragma unroll
        for (int p = 0; p < 16; p++) {
            float4 o = acc[p];
            o.x += bv.x; o.y += bv.y; o.z += bv.z; o.w += bv.w;
            xP4[(16 * tpg + p) * XP4 + tc6] = o;
        }
    }

    // resblock 0 (mm_dual's first sync orders xP writes & frees peP/fcwc region)
    int tc = tid & 31, tp = tid >> 5;
    float4 accH[8], accS[8];
#pragma unroll
    for (int p = 0; p < 8; p++) { accH[p] = make_float4(0.f,0.f,0.f,0.f); accS[p] = accH[p]; }
    mm_dual256(xP, w0g, wsg, wbuf, accH, accS, tc, tp, tid);
    resblock_tail(hP, wbuf, b0g, w1g, b1g, accH, accS, tc, tp, tid, pt0);
}

// ---------------- resblock i (with pooled-feature gather) ----------------
__global__ __launch_bounds__(256, 2) void resblock_kernel(
    const float* __restrict__ w0g, const float* __restrict__ b0g,
    const float* __restrict__ w1g, const float* __restrict__ b1g,
    const float* __restrict__ wsg)
{
    extern __shared__ float sm[];
    float* xP   = sm;                          // 64*264
    float* wbuf = sm + 64 * XPIT;              // 2*32*128
    int*   idx_s = (int*)(wbuf + 2 * 32 * 128);// 64
    float* hP   = xP;                          // overlay

    int tid = threadIdx.x;
    int tc = tid & 31, tp = tid >> 5;
    int pt0 = blockIdx.x * PT;
    int b = pt0 >> 16;

    if (tid < PT) idx_s[tid] = g_index[pt0 + tid];
    __syncthreads();

    // x = concat(net, pooled) -> point-major smem (conflict-free f4 stores)
    const float4* net4 = (const float4*)&g_net[(size_t)pt0 * HD];
    float4* xP4 = (float4*)xP;
#pragma unroll
    for (int l = 0; l < 16; l++) {
        int fi = tid + l * 256;      // 0..4095 = 64 pts x 64 f4
        int p = fi >> 6, q = fi & 63;
        float4 v;
        if (q < 32) v = net4[p * 32 + q];
        else        v = *(((const float4*)&g_grid[(size_t)(b * GV + idx_s[p]) * HD]) + (q - 32));
        xP4[p * XP4 + q] = v;
    }

    float4 accH[8], accS[8];
#pragma unroll
    for (int p = 0; p < 8; p++) { accH[p] = make_float4(0.f,0.f,0.f,0.f); accS[p] = accH[p]; }
    mm_dual256(xP, w0g, wsg, wbuf, accH, accS, tc, tp, tid);   // first sync orders xP
    resblock_tail(hP, wbuf, b0g, w1g, b1g, accH, accS, tc, tp, tid, pt0);
}

// ---------------- scatter max pool: net -> grid ----------------
__global__ __launch_bounds__(256) void scatter_max_kernel()
{
    int gw = (blockIdx.x * 256 + threadIdx.x) >> 5;   // point id
    int lane = threadIdx.x & 31;
    int b = gw >> 16;
    int v = g_index[gw];
    float4 val = *(((const float4*)&g_net[(size_t)gw * HD]) + lane);
    float* dst = &g_grid[(size_t)(b * GV + v) * HD + 4 * lane];
    atomic_max_f(dst + 0, val.x);
    atomic_max_f(dst + 1, val.y);
    atomic_max_f(dst + 2, val.z);
    atomic_max_f(dst + 3, val.w);
}

// ---------------- final fc_c + scatter add ----------------
__global__ __launch_bounds__(256, 2) void final_kernel(
    const float* __restrict__ wcg, const float* __restrict__ bcg)
{
    extern __shared__ float sm[];
    float* xP   = sm;                       // 64*132
    float* wbuf = sm + 64 * HPIT;           // 32*128
    int*   idx_s = (int*)(wbuf + 32 * 128);

    int tid = threadIdx.x;
    int tc = tid & 31, tp = tid >> 5;
    int pt0 = blockIdx.x * PT;
    int b = pt0 >> 16;

    if (tid < PT) idx_s[tid] = g_index[pt0 + tid];

    const float4* net4 = (const float4*)&g_net[(size_t)pt0 * HD];
    float4* xP4 = (float4*)xP;
#pragma unroll
    for (int l = 0; l < 8; l++) {
        int fi = tid + l * 256;      // 0..2047 = 64 pts x 32 f4
        int p = fi >> 5, q = fi & 31;
        xP4[p * HP4 + q] = net4[p * 32 + q];
    }

    float4 acc[8];
#pragma unroll
    for (int p = 0; p < 8; p++) acc[p] = make_float4(0.f, 0.f, 0.f, 0.f);
    mm_single<128, HPIT>(xP, wcg, wbuf, acc, tc, tp, tid);   // sync covers xP & idx_s

    float4 bv = *(const float4*)(bcg + 4 * tc);
#pragma unroll
    for (int p = 0; p < 8; p++) {
        int pp = 8 * tp + p;
        float* dst = &g_grid[(size_t)(b * GV + idx_s[pp]) * HD + 4 * tc];
        atomicAdd(dst + 0, acc[p].x + bv.x);
        atomicAdd(dst + 1, acc[p].y + bv.y);
        atomicAdd(dst + 2, acc[p].z + bv.z);
        atomicAdd(dst + 3, acc[p].w + bv.w);
    }
    if (tid < PT) atomicAdd(&g_cnt[b * GV + idx_s[tid]], 1.0f);
}

// ---------------- finalize: mean + transpose to [B,C,32,32,32] ----------------
__global__ __launch_bounds__(256) void finalize_kernel(float* __restrict__ out)
{
    __shared__ float s[32 * 129];
    __shared__ float inv[32];
    int tid = threadIdx.x;
    int blk = blockIdx.x;             // 0..4095
    int b = blk >> 10;
    int v0 = (blk & 1023) * 32;

    const float4* src = (const float4*)&g_grid[(size_t)(b * GV + v0) * HD];
#pragma unroll
    for (int l = 0; l < 4; l++) {
        int fi = tid + l * 256;       // 0..1023 (32 voxels x 32 f4)
        int vv = fi >> 5, q = fi & 31;
        float4 x = src[vv * 32 + q];
        s[vv * 129 + 4 * q + 0] = x.x;
        s[vv * 129 + 4 * q + 1] = x.y;
        s[vv * 129 + 4 * q + 2] = x.z;
        s[vv * 129 + 4 * q + 3] = x.w;
    }
    if (tid < 32) inv[tid] = 1.0f / fmaxf(g_cnt[b * GV + v0 + tid], 1.0f);
    __syncthreads();

    float* ob = out + (size_t)b * HD * GV + v0;
#pragma unroll
    for (int l = 0; l < 16; l++) {
        int oi = tid + l * 256;       // 128 ch x 32 voxels
        int ch = oi >> 5, vv = oi & 31;
        ob[(size_t)ch * GV + vv] = s[vv * 129 + ch] * inv[vv];
    }
}

// ---------------- fills ----------------
__global__ void fill_grid_kernel(unsigned int val)
{
    int i = blockIdx.x * 256 + threadIdx.x;   // uint4 index; total 4194304
    ((uint4*)g_grid)[i] = make_uint4(val, val, val, val);
}
__global__ void fill_cnt_kernel()
{
    int i = blockIdx.x * 256 + threadIdx.x;
    if (i < NB * GV) g_cnt[i] = 0.0f;
}

// ---------------- host ----------------
extern "C" void kernel_launch(void* const* d_in, const int* in_sizes, int n_in,
                              void* d_out, int out_size)
{
    const float* p        = (const float*)d_in[0];
    const float* fc_pos_w = (const float*)d_in[1];
    const float* fc_pos_b = (const float*)d_in[2];
    const float* fc0_w    = (const float*)d_in[3];
    const float* fc0_b    = (const float*)d_in[4];
    const float* fc1_w    = (const float*)d_in[5];
    const float* fc1_b    = (const float*)d_in[6];
    const float* sc_w     = (const float*)d_in[7];
    const float* fc_c_w   = (const float*)d_in[8];
    const float* fc_c_b   = (const float*)d_in[9];
    float* out = (float*)d_out;

    const int SMEM_IN = (64 * XPIT + 4096 + 5120) * 4;           // 104448
    const int SMEM_RB = (64 * XPIT + 2 * 32 * 128) * 4 + 256;    // 100608
    const int SMEM_FC = (64 * HPIT + 32 * 128) * 4 + 256;        // 50432

    cudaFuncSetAttribute(input_kernel,    cudaFuncAttributeMaxDynamicSharedMemorySize, SMEM_IN);
    cudaFuncSetAttribute(resblock_kernel, cudaFuncAttributeMaxDynamicSharedMemorySize, SMEM_RB);
    cudaFuncSetAttribute(final_kernel,    cudaFuncAttributeMaxDynamicSharedMemorySize, SMEM_FC);

    const int NTILES = NB * TPTS / PT;    // 4096

    input_kernel<<<NTILES, 256, SMEM_IN>>>(p, fc_pos_w, fc_pos_b,
                                           fc0_w, fc0_b, fc1_w, fc1_b, sc_w);

    for (int i = 1; i < 5; i++) {
        fill_grid_kernel<<<16384, 256>>>(0xFFFFFFFFu);
        scatter_max_kernel<<<NB * TPTS / 8, 256>>>();
        resblock_kernel<<<NTILES, 256, SMEM_RB>>>(fc0_w + i * 256 * 128,
                                                  fc0_b + i * 128,
                                                  fc1_w + i * 128 * 128,
                                                  fc1_b + i * 128,
                                                  sc_w + i * 256 * 128);
    }

    fill_grid_kernel<<<16384, 256>>>(0u);
    fill_cnt_kernel<<<512, 256>>>();
    final_kernel<<<NTILES, 256, SMEM_FC>>>(fc_c_w, fc_c_b);
    finalize_kernel<<<NB * GV / 32, 256>>>(out);
}

// round 8
// speedup vs baseline: 1.7462x; 1.4994x over previous
#include <cuda_runtime.h>
#include <cuda_bf16.h>
#include <cstdint>

// Problem constants
#define NB    4
#define TPTS  65536
#define GV    32768          // 32^3 voxels
#define HD    128
#define PT    64             // points per tile (scalar kernels)
#define HPIT  132
#define HP4   33

// ---------------- scratch (no cudaMalloc allowed) ----------------
__device__ __align__(16) float g_net[33554432];    // [4][65536][128]
__device__ __align__(16) int   g_index[262144];    // [4][65536]
__device__ __align__(16) float g_grid[16777216];   // [4][32768][128]
__device__ __align__(16) float g_cnt[131072];      // [4][32768]
__device__ __align__(16) float g_xcat[67108864];   // [4][65536][256] fc_pos output
__device__ __align__(16) __nv_bfloat16 g_hh[33554432];  // hidden h hi
__device__ __align__(16) __nv_bfloat16 g_hl[33554432];  // hidden h lo

// prepared bf16 weights, transposed to [blk][n][k], hi/lo split
__device__ __align__(16) __nv_bfloat16 t_w0h[163840], t_w0l[163840];
__device__ __align__(16) __nv_bfloat16 t_wsh[163840], t_wsl[163840];
__device__ __align__(16) __nv_bfloat16 t_w1h[81920],  t_w1l[81920];

// ---------------- helpers ----------------
__device__ __forceinline__ uint32_t smem_u32(const void* p) {
    uint32_t a;
    asm("{ .reg .u64 t; cvta.to.shared.u64 t, %1; cvt.u32.u64 %0, t; }" : "=r"(a) : "l"(p));
    return a;
}
__device__ __forceinline__ void ldsm4(uint32_t r[4], uint32_t addr) {
    asm volatile("ldmatrix.sync.aligned.m8n8.x4.shared.b16 {%0,%1,%2,%3}, [%4];"
                 : "=r"(r[0]), "=r"(r[1]), "=r"(r[2]), "=r"(r[3]) : "r"(addr));
}
__device__ __forceinline__ void mma16816(float* d, const uint32_t a[4], uint32_t b0, uint32_t b1) {
    asm volatile(
        "mma.sync.aligned.m16n8k16.row.col.f32.bf16.bf16.f32 "
        "{%0,%1,%2,%3}, {%4,%5,%6,%7}, {%8,%9}, {%0,%1,%2,%3};"
        : "+f"(d[0]), "+f"(d[1]), "+f"(d[2]), "+f"(d[3])
        : "r"(a[0]), "r"(a[1]), "r"(a[2]), "r"(a[3]), "r"(b0), "r"(b1));
}
__device__ __forceinline__ uint32_t pack_hi(float a, float b, uint32_t& lo_out) {
    __nv_bfloat16 ha = __float2bfloat16(a);
    __nv_bfloat16 hb = __float2bfloat16(b);
    float la = a - __bfloat162float(ha);
    float lb = b - __bfloat162float(hb);
    __nv_bfloat16 lab = __float2bfloat16(la);
    __nv_bfloat16 lbb = __float2bfloat16(lb);
    lo_out = ((uint32_t)__bfloat16_as_ushort(lbb) << 16) | __bfloat16_as_ushort(lab);
    return ((uint32_t)__bfloat16_as_ushort(hb) << 16) | __bfloat16_as_ushort(ha);
}
__device__ __forceinline__ void fma4(float4& a, float s, float4 w) {
    a.x = fmaf(s, w.x, a.x); a.y = fmaf(s, w.y, a.y);
    a.z = fmaf(s, w.z, a.z); a.w = fmaf(s, w.w, a.w);
}
__device__ __forceinline__ void atomic_max_f(float* a, float v) {
    unsigned int uv = __float_as_uint(v);
    if (uv >> 31) atomicMin((unsigned int*)a, uv);
    else          atomicMax((int*)a, (int)uv);
}
template <int KIN, int PITCH>
__device__ __forceinline__ void mm_single(
    const float* __restrict__ xP, const float* __restrict__ wg, float* wbuf,
    float4 acc[8], int tc, int tp, int tid)
{
    float4* wc = (float4*)wbuf;
    for (int kc = 0; kc < KIN; kc += 32) {
        __syncthreads();
        const float4* ws = (const float4*)(wg + kc * 128);
#pragma unroll
        for (int l = 0; l < 4; l++) wc[tid + l * 256] = ws[tid + l * 256];
        __syncthreads();
#pragma unroll 2
        for (int s = 0; s < 8; s++) {
            float4 w0 = wc[(4 * s + 0) * 32 + tc];
            float4 w1 = wc[(4 * s + 1) * 32 + tc];
            float4 w2 = wc[(4 * s + 2) * 32 + tc];
            float4 w3 = wc[(4 * s + 3) * 32 + tc];
            const float* xb = xP + kc + 4 * s + (8 * tp) * PITCH;
#pragma unroll
            for (int p = 0; p < 8; p++) {
                float4 xv = *(const float4*)(xb + p * PITCH);
                fma4(acc[p], xv.x, w0); fma4(acc[p], xv.y, w1);
                fma4(acc[p], xv.z, w2); fma4(acc[p], xv.w, w3);
            }
        }
    }
}

// ---------------- weight prep: fp32 -> transposed bf16 hi/lo ----------------
__global__ void prep_weights(const float* __restrict__ w0, const float* __restrict__ w1,
                             const float* __restrict__ ws)
{
    int i = blockIdx.x * 256 + threadIdx.x;
    if (i < 163840) {
        int blk = i >> 15, r = i & 32767;
        int k = r >> 7, n = r & 127;
        float v0 = w0[i], vs = ws[i];
        __nv_bfloat16 h0 = __float2bfloat16(v0);
        __nv_bfloat16 hs = __float2bfloat16(vs);
        int o = (blk << 15) + n * 256 + k;
        t_w0h[o] = h0; t_w0l[o] = __float2bfloat16(v0 - __bfloat162float(h0));
        t_wsh[o] = hs; t_wsl[o] = __float2bfloat16(vs - __bfloat162float(hs));
    } else if (i < 245760) {
        int j = i - 163840;
        int blk = j >> 14, r = j & 16383;
        int k = r >> 7, n = r & 127;
        float v = w1[j];
        __nv_bfloat16 h = __float2bfloat16(v);
        int o = (blk << 14) + (n << 7) + k;
        t_w1h[o] = h; t_w1l[o] = __float2bfloat16(v - __bfloat162float(h));
    }
}

// ---------------- input: index + pos-enc + fc_pos -> g_xcat ----------------
__global__ __launch_bounds__(256) void input_kernel(
    const float* __restrict__ pg,
    const float* __restrict__ fcpw, const float* __restrict__ fcpb)
{
    extern __shared__ float sm[];
    float* peP  = sm;            // 64*64
    float* fcwc = sm + 4096;     // 20*256

    int tid = threadIdx.x;
    int pt0 = blockIdx.x * PT;

    if (tid < PT) {
        int pt = pt0 + tid;
        float px = pg[pt * 3 + 0], py = pg[pt * 3 + 1], pz = pg[pt * 3 + 2];
        const float hi = 1.0f - 1e-3f;
        float nx = fminf(fmaxf(px / 1.101f + 0.5f, 0.0f), hi);
        float ny = fminf(fmaxf(py / 1.101f + 0.5f, 0.0f), hi);
        float nz = fminf(fmaxf(pz / 1.101f + 0.5f, 0.0f), hi);
        int xi = (int)(nx * 32.0f), yi = (int)(ny * 32.0f), zi = (int)(nz * 32.0f);
        g_index[pt] = xi + 32 * (yi + 32 * zi);
    }

#pragma unroll
    for (int l = 0; l < 8; l++) {
        int task = tid + l * 256;
        if (task < PT * 30) {
            int pi = task / 30, j = task % 30;
            int fr = j / 3, coord = j % 3;
            float pv = pg[(pt0 + pi) * 3 + coord];
            float f = exp2f((float)fr) * 3.14159265358979323846f;
            float s, c;
            sincosf(f * pv, &s, &c);
            peP[pi * 64 + fr * 6 + coord]     = s;
            peP[pi * 64 + fr * 6 + 3 + coord] = c;
        }
    }

    int tc6 = tid & 63, tpg = tid >> 6;
    float4 acc[16];
#pragma unroll
    for (int p = 0; p < 16; p++) acc[p] = make_float4(0.f, 0.f, 0.f, 0.f);
    for (int kc = 0; kc < 60; kc += 20) {
        __syncthreads();
        const float4* ws = (const float4*)(fcpw + kc * 256);
#pragma unroll
        for (int l = 0; l < 5; l++) ((float4*)fcwc)[tid + l * 256] = ws[tid + l * 256];
        __syncthreads();
#pragma unroll 2
        for (int s = 0; s < 10; s++) {
            float4 w0 = ((float4*)fcwc)[(2 * s + 0) * 64 + tc6];
            float4 w1 = ((float4*)fcwc)[(2 * s + 1) * 64 + tc6];
            const float* xb = peP + (16 * tpg) * 64 + kc + 2 * s;
#pragma unroll
            for (int p = 0; p < 16; p++) {
                float2 xv = *(const float2*)(xb + p * 64);
                fma4(acc[p], xv.x, w0);
                fma4(acc[p], xv.y, w1);
            }
        }
    }
    float4 bv = *(const float4*)(fcpb + 4 * tc6);
#pragma unroll
    for (int p = 0; p < 16; p++) {
        float4 o = acc[p];
        o.x += bv.x; o.y += bv.y; o.z += bv.z; o.w += bv.w;
        *(float4*)(g_xcat + (size_t)(pt0 + 16 * tpg + p) * 256 + 4 * tc6) = o;
    }
}

// ---------------- HMMA resblock ----------------
// smem layout (bytes)
#define SM_AHI 0
#define SM_ALO 16384
#define SM_BHI 32768
#define SM_BLO 49152
#define SM_B0  65536
#define SM_B1  66048
#define SM_IDX 66560
#define SMEM_RBT 67072

// A chunk loader: fp32 sources -> bf16 hi/lo swizzled smem tiles [128][64]
__device__ __forceinline__ void load_a_fp32(char* smraw, int mode, int c, int pt0, int b,
                                            const int* idx_s, int tid)
{
#pragma unroll
    for (int i = 0; i < 16; i++) {
        int u = tid + i * 256;          // 0..4095
        int r = u >> 5, j2 = u & 31;
        const float* src;
        if (mode == 0)   src = g_xcat + (size_t)(pt0 + r) * 256 + c * 64;
        else if (c < 2)  src = g_net + (size_t)(pt0 + r) * 128 + c * 64;
        else             src = g_grid + ((size_t)b * GV + idx_s[r]) * 128 + (c - 2) * 64;
        float2 v = *(const float2*)(src + 2 * j2);
        uint32_t ul;
        uint32_t uh = pack_hi(v.x, v.y, ul);
        uint32_t off = r * 128 + 4 * j2;
        uint32_t sw = off ^ ((off >> 3) & 0x70);
        *(uint32_t*)(smraw + SM_AHI + sw) = uh;
        *(uint32_t*)(smraw + SM_ALO + sw) = ul;
    }
}

// A chunk loader from prepared bf16 h (hi/lo already split)
__device__ __forceinline__ void load_a_h(char* smraw, int c, int pt0, int tid)
{
#pragma unroll
    for (int i = 0; i < 16; i++) {
        int u = tid + i * 256;
        int r = u >> 5, j2 = u & 31;
        size_t si = (size_t)(pt0 + r) * 128 + c * 64 + 2 * j2;
        uint32_t off = r * 128 + 4 * j2;
        uint32_t sw = off ^ ((off >> 3) & 0x70);
        *(uint32_t*)(smraw + SM_AHI + sw) = *(const uint32_t*)&g_hh[si];
        *(uint32_t*)(smraw + SM_ALO + sw) = *(const uint32_t*)&g_hl[si];
    }
}

// B chunk loader: [128n][64k] bf16 hi/lo tiles from [n][K] weights
__device__ __forceinline__ void load_b(char* smraw, const __nv_bfloat16* wh,
                                       const __nv_bfloat16* wl, int rowStride16, int c, int tid)
{
    const uint4* wh4 = (const uint4*)wh;
    const uint4* wl4 = (const uint4*)wl;
#pragma unroll
    for (int i = 0; i < 4; i++) {
        int u = tid + i * 256;          // 0..1023
        int row = u >> 3, j = u & 7;
        uint32_t off = row * 128 + j * 16;
        uint32_t sw = off ^ ((off >> 3) & 0x70);
        *(uint4*)(smraw + SM_BHI + sw) = wh4[row * rowStride16 + c * 8 + j];
        *(uint4*)(smraw + SM_BLO + sw) = wl4[row * rowStride16 + c * 8 + j];
    }
}

// one K=64 chunk of split-bf16 MMAs; warp tile M=32 (wm), N=64 (wn)
template <bool RELU>
__device__ __forceinline__ void chunk_mma(uint32_t sb, float* d, int lane, int wm, int wn)
{
    int arow0 = wm * 32 + ((lane >> 3) & 1) * 8 + (lane & 7);
    int acol  = ((lane >> 4) & 1) * 16;
    int brow0 = wn * 64 + ((lane >> 4) & 1) * 8 + (lane & 7);
    int bcol  = ((lane >> 3) & 1) * 16;
#pragma unroll
    for (int ks = 0; ks < 4; ks++) {
        uint32_t ah[2][4], al[2][4];
#pragma unroll
        for (int mt = 0; mt < 2; mt++) {
            uint32_t off = (uint32_t)(arow0 + mt * 16) * 128 + ks * 32 + acol;
            uint32_t sw = off ^ ((off >> 3) & 0x70);
            ldsm4(ah[mt], sb + SM_AHI + sw);
            ldsm4(al[mt], sb + SM_ALO + sw);
            if (RELU) {
#pragma unroll
                for (int i = 0; i < 4; i++) {
                    uint32_t m = ((~ah[mt][i]) >> 15) & 0x00010001u;
                    m *= 0xFFFFu;
                    ah[mt][i] &= m;
                    al[mt][i] &= m;
                }
            }
        }
#pragma unroll
        for (int ntp = 0; ntp < 4; ntp++) {
            uint32_t off = (uint32_t)(brow0 + ntp * 16) * 128 + ks * 32 + bcol;
            uint32_t sw = off ^ ((off >> 3) & 0x70);
            uint32_t bh[4], bl[4];
            ldsm4(bh, sb + SM_BHI + sw);
            ldsm4(bl, sb + SM_BLO + sw);
#pragma unroll
            for (int mt = 0; mt < 2; mt++) {
                float* dp = d + (mt * 8 + ntp * 2) * 4;
                mma16816(dp, ah[mt], bh[0], bh[1]);
                mma16816(dp, al[mt], bh[0], bh[1]);
                mma16816(dp, ah[mt], bl[0], bl[1]);
                mma16816(dp + 4, ah[mt], bh[2], bh[3]);
                mma16816(dp + 4, al[mt], bh[2], bh[3]);
                mma16816(dp + 4, ah[mt], bl[2], bl[3]);
            }
        }
    }
}

__global__ __launch_bounds__(256, 2) void resblock_hmma(
    int mode, int blk, const float* __restrict__ b0g, const float* __restrict__ b1g)
{
    extern __shared__ char smraw[];
    uint32_t sb = smem_u32(smraw);
    float* bias0 = (float*)(smraw + SM_B0);
    float* bias1 = (float*)(smraw + SM_B1);
    int*   idx_s = (int*)(smraw + SM_IDX);

    int tid = threadIdx.x, lane = tid & 31, w = tid >> 5;
    int wm = w & 3, wn = w >> 2;
    int pt0 = blockIdx.x * 128;
    int b = pt0 >> 16;

    if (tid < 128) {
        bias0[tid] = b0g[tid];
        bias1[tid] = b1g[tid];
        idx_s[tid] = g_index[pt0 + tid];
    }
    __syncthreads();

    float d[64];
#pragma unroll
    for (int i = 0; i < 64; i++) d[i] = 0.f;

    // ---- pass H: D = relu(x) @ W0, K=256 ----
    for (int c = 0; c < 4; c++) {
        load_a_fp32(smraw, mode, c, pt0, b, idx_s, tid);
        load_b(smraw, t_w0h + blk * 32768, t_w0l + blk * 32768, 32, c, tid);
        __syncthreads();
        chunk_mma<true>(sb, d, lane, wm, wn);
        __syncthreads();
    }
    // h = relu(D + b0) -> g_hh/g_hl (bf16 hi/lo)
    {
        int rbase = wm * 32 + (lane >> 2);
        int cbase = wn * 64 + (lane & 3) * 2;
#pragma unroll
        for (int mt = 0; mt < 2; mt++) {
            int r0 = pt0 + rbase + mt * 16;
#pragma unroll
            for (int nt = 0; nt < 8; nt++) {
                int c0 = cbase + nt * 8;
                const float* dd = d + (mt * 8 + nt) * 4;
                float b0a = bias0[c0], b0b = bias0[c0 + 1];
                float v0 = fmaxf(dd[0] + b0a, 0.f), v1 = fmaxf(dd[1] + b0b, 0.f);
                float v2 = fmaxf(dd[2] + b0a, 0.f), v3 = fmaxf(dd[3] + b0b, 0.f);
                uint32_t l01, l23;
                uint32_t h01 = pack_hi(v0, v1, l01);
                uint32_t h23 = pack_hi(v2, v3, l23);
                *(uint32_t*)&g_hh[(size_t)r0 * 128 + c0] = h01;
                *(uint32_t*)&g_hl[(size_t)r0 * 128 + c0] = l01;
                *(uint32_t*)&g_hh[(size_t)(r0 + 8) * 128 + c0] = h23;
                *(uint32_t*)&g_hl[(size_t)(r0 + 8) * 128 + c0] = l23;
            }
        }
    }
#pragma unroll
    for (int i = 0; i < 64; i++) d[i] = 0.f;

    // ---- pass S: D = x @ Ws, K=256 ----
    for (int c = 0; c < 4; c++) {
        load_a_fp32(smraw, mode, c, pt0, b, idx_s, tid);
        load_b(smraw, t_wsh + blk * 32768, t_wsl + blk * 32768, 32, c, tid);
        __syncthreads();
        chunk_mma<false>(sb, d, lane, wm, wn);
        __syncthreads();
    }
    // ---- stage 2: D += h @ W1, K=128 (h written above; __syncthreads chain orders it) ----
    for (int c = 0; c < 2; c++) {
        load_a_h(smraw, c, pt0, tid);
        load_b(smraw, t_w1h + blk * 16384, t_w1l + blk * 16384, 16, c, tid);
        __syncthreads();
        chunk_mma<false>(sb, d, lane, wm, wn);
        __syncthreads();
    }
    // out = D + b1 -> g_net
    {
        int rbase = wm * 32 + (lane >> 2);
        int cbase = wn * 64 + (lane & 3) * 2;
#pragma unroll
        for (int mt = 0; mt < 2; mt++) {
            int r0 = pt0 + rbase + mt * 16;
#pragma unroll
            for (int nt = 0; nt < 8; nt++) {
                int c0 = cbase + nt * 8;
                const float* dd = d + (mt * 8 + nt) * 4;
                float b1a = bias1[c0], b1b = bias1[c0 + 1];
                float2 o0 = make_float2(dd[0] + b1a, dd[1] + b1b);
                float2 o1 = make_float2(dd[2] + b1a, dd[3] + b1b);
                *(float2*)&g_net[(size_t)r0 * 128 + c0] = o0;
                *(float2*)&g_net[(size_t)(r0 + 8) * 128 + c0] = o1;
            }
        }
    }
}

// ---------------- scatter max pool: net -> grid ----------------
__global__ __launch_bounds__(256) void scatter_max_kernel()
{
    int gw = (blockIdx.x * 256 + threadIdx.x) >> 5;
    int lane = threadIdx.x & 31;
    int b = gw >> 16;
    int v = g_index[gw];
    float4 val = *(((const float4*)&g_net[(size_t)gw * HD]) + lane);
    float* dst = &g_grid[(size_t)(b * GV + v) * HD + 4 * lane];
    atomic_max_f(dst + 0, val.x);
    atomic_max_f(dst + 1, val.y);
    atomic_max_f(dst + 2, val.z);
    atomic_max_f(dst + 3, val.w);
}

// ---------------- final fc_c + scatter add ----------------
__global__ __launch_bounds__(256, 2) void final_kernel(
    const float* __restrict__ wcg, const float* __restrict__ bcg)
{
    extern __shared__ float sm[];
    float* xP   = sm;
    float* wbuf = sm + 64 * HPIT;
    int*   idx_s = (int*)(wbuf + 32 * 128);

    int tid = threadIdx.x;
    int tc = tid & 31, tp = tid >> 5;
    int pt0 = blockIdx.x * PT;
    int b = pt0 >> 16;

    if (tid < PT) idx_s[tid] = g_index[pt0 + tid];

    const float4* net4 = (const float4*)&g_net[(size_t)pt0 * HD];
    float4* xP4 = (float4*)xP;
#pragma unroll
    for (int l = 0; l < 8; l++) {
        int fi = tid + l * 256;
        int p = fi >> 5, q = fi & 31;
        xP4[p * HP4 + q] = net4[p * 32 + q];
    }

    float4 acc[8];
#pragma unroll
    for (int p = 0; p < 8; p++) acc[p] = make_float4(0.f, 0.f, 0.f, 0.f);
    mm_single<128, HPIT>(xP, wcg, wbuf, acc, tc, tp, tid);

    float4 bv = *(const float4*)(bcg + 4 * tc);
#pragma unroll
    for (int p = 0; p < 8; p++) {
        int pp = 8 * tp + p;
        float* dst = &g_grid[(size_t)(b * GV + idx_s[pp]) * HD + 4 * tc];
        atomicAdd(dst + 0, acc[p].x + bv.x);
        atomicAdd(dst + 1, acc[p].y + bv.y);
        atomicAdd(dst + 2, acc[p].z + bv.z);
        atomicAdd(dst + 3, acc[p].w + bv.w);
    }
    if (tid < PT) atomicAdd(&g_cnt[b * GV + idx_s[tid]], 1.0f);
}

// ---------------- finalize: mean + transpose ----------------
__global__ __launch_bounds__(256) void finalize_kernel(float* __restrict__ out)
{
    __shared__ float s[32 * 129];
    __shared__ float inv[32];
    int tid = threadIdx.x;
    int blk = blockIdx.x;
    int b = blk >> 10;
    int v0 = (blk & 1023) * 32;

    const float4* src = (const float4*)&g_grid[(size_t)(b * GV + v0) * HD];
#pragma unroll
    for (int l = 0; l < 4; l++) {
        int fi = tid + l * 256;
        int vv = fi >> 5, q = fi & 31;
        float4 x = src[vv * 32 + q];
        s[vv * 129 + 4 * q + 0] = x.x;
        s[vv * 129 + 4 * q + 1] = x.y;
        s[vv * 129 + 4 * q + 2] = x.z;
        s[vv * 129 + 4 * q + 3] = x.w;
    }
    if (tid < 32) inv[tid] = 1.0f / fmaxf(g_cnt[b * GV + v0 + tid], 1.0f);
    __syncthreads();

    float* ob = out + (size_t)b * HD * GV + v0;
#pragma unroll
    for (int l = 0; l < 16; l++) {
        int oi = tid + l * 256;
        int ch = oi >> 5, vv = oi & 31;
        ob[(size_t)ch * GV + vv] = s[vv * 129 + ch] * inv[vv];
    }
}

// ---------------- fills ----------------
__global__ void fill_grid_kernel(unsigned int val)
{
    int i = blockIdx.x * 256 + threadIdx.x;
    ((uint4*)g_grid)[i] = make_uint4(val, val, val, val);
}
__global__ void fill_cnt_kernel()
{
    int i = blockIdx.x * 256 + threadIdx.x;
    if (i < NB * GV) g_cnt[i] = 0.0f;
}

// ---------------- host ----------------
extern "C" void kernel_launch(void* const* d_in, const int* in_sizes, int n_in,
                              void* d_out, int out_size)
{
    const float* p        = (const float*)d_in[0];
    const float* fc_pos_w = (const float*)d_in[1];
    const float* fc_pos_b = (const float*)d_in[2];
    const float* fc0_w    = (const float*)d_in[3];
    const float* fc0_b    = (const float*)d_in[4];
    const float* fc1_w    = (const float*)d_in[5];
    const float* fc1_b    = (const float*)d_in[6];
    const float* sc_w     = (const float*)d_in[7];
    const float* fc_c_w   = (const float*)d_in[8];
    const float* fc_c_b   = (const float*)d_in[9];
    float* out = (float*)d_out;

    const int SMEM_IN = (4096 + 5120) * 4;                       // 36864
    const int SMEM_FC = (64 * HPIT + 32 * 128) * 4 + 256;        // 50432

    cudaFuncSetAttribute(input_kernel,    cudaFuncAttributeMaxDynamicSharedMemorySize, SMEM_IN);
    cudaFuncSetAttribute(resblock_hmma,   cudaFuncAttributeMaxDynamicSharedMemorySize, SMEM_RBT);
    cudaFuncSetAttribute(final_kernel,    cudaFuncAttributeMaxDynamicSharedMemorySize, SMEM_FC);

    prep_weights<<<960, 256>>>(fc0_w, fc1_w, sc_w);
    input_kernel<<<NB * TPTS / PT, 256, SMEM_IN>>>(p, fc_pos_w, fc_pos_b);

    const int TNT = NB * TPTS / 128;   // 2048 tiles

    resblock_hmma<<<TNT, 256, SMEM_RBT>>>(0, 0, fc0_b, fc1_b);

    for (int i = 1; i < 5; i++) {
        fill_grid_kernel<<<16384, 256>>>(0xFFFFFFFFu);
        scatter_max_kernel<<<NB * TPTS / 8, 256>>>();
        resblock_hmma<<<TNT, 256, SMEM_RBT>>>(1, i, fc0_b + i * 128, fc1_b + i * 128);
    }

    fill_grid_kernel<<<16384, 256>>>(0u);
    fill_cnt_kernel<<<512, 256>>>();
    final_kernel<<<NB * TPTS / PT, 256, SMEM_FC>>>(fc_c_w, fc_c_b);
    finalize_kernel<<<NB * GV / 32, 256>>>(out);
}

// round 9
// speedup vs baseline: 1.8899x; 1.0823x over previous
#include <cuda_runtime.h>
#include <cuda_bf16.h>
#include <cstdint>

// Problem constants
#define NB    4
#define TPTS  65536
#define GV    32768          // 32^3 voxels
#define HD    128
#define PT    64             // points per tile (input kernel)

// ---------------- scratch (no cudaMalloc allowed) ----------------
__device__ __align__(16) int   g_index[262144];          // [4][65536]
__device__ __align__(16) float g_grid[16777216];         // [4][32768][128] fp32 (atomics)
__device__ __align__(16) float g_cnt[131072];            // [4][32768]
__device__ __align__(16) __nv_bfloat16 g_xh[67108864];   // [4][65536][256] x hi
__device__ __align__(16) __nv_bfloat16 g_xl[67108864];   // x lo
__device__ __align__(16) __nv_bfloat16 g_nh[33554432];   // [4][65536][128] net hi
__device__ __align__(16) __nv_bfloat16 g_nl[33554432];   // net lo
__device__ __align__(16) __nv_bfloat16 g_hh[33554432];   // hidden h hi
__device__ __align__(16) __nv_bfloat16 g_hl[33554432];   // hidden h lo
__device__ __align__(16) __nv_bfloat16 g_ph[16777216];   // [4][32768][128] pooled hi
__device__ __align__(16) __nv_bfloat16 g_pl[16777216];   // pooled lo

// prepared bf16 weights, transposed to [blk][n][k], hi/lo split
__device__ __align__(16) __nv_bfloat16 t_w0h[163840], t_w0l[163840];
__device__ __align__(16) __nv_bfloat16 t_wsh[163840], t_wsl[163840];
__device__ __align__(16) __nv_bfloat16 t_w1h[81920],  t_w1l[81920];
__device__ __align__(16) __nv_bfloat16 t_wch[16384],  t_wcl[16384];

// ---------------- helpers ----------------
__device__ __forceinline__ uint32_t smem_u32(const void* p) {
    uint32_t a;
    asm("{ .reg .u64 t; cvta.to.shared.u64 t, %1; cvt.u32.u64 %0, t; }" : "=r"(a) : "l"(p));
    return a;
}
__device__ __forceinline__ void ldsm4(uint32_t r[4], uint32_t addr) {
    asm volatile("ldmatrix.sync.aligned.m8n8.x4.shared.b16 {%0,%1,%2,%3}, [%4];"
                 : "=r"(r[0]), "=r"(r[1]), "=r"(r[2]), "=r"(r[3]) : "r"(addr));
}
__device__ __forceinline__ void mma16816(float* d, const uint32_t a[4], uint32_t b0, uint32_t b1) {
    asm volatile(
        "mma.sync.aligned.m16n8k16.row.col.f32.bf16.bf16.f32 "
        "{%0,%1,%2,%3}, {%4,%5,%6,%7}, {%8,%9}, {%0,%1,%2,%3};"
        : "+f"(d[0]), "+f"(d[1]), "+f"(d[2]), "+f"(d[3])
        : "r"(a[0]), "r"(a[1]), "r"(a[2]), "r"(a[3]), "r"(b0), "r"(b1));
}
__device__ __forceinline__ uint32_t pack_hi(float a, float b, uint32_t& lo_out) {
    __nv_bfloat16 ha = __float2bfloat16(a);
    __nv_bfloat16 hb = __float2bfloat16(b);
    float la = a - __bfloat162float(ha);
    float lb = b - __bfloat162float(hb);
    __nv_bfloat16 lab = __float2bfloat16(la);
    __nv_bfloat16 lbb = __float2bfloat16(lb);
    lo_out = ((uint32_t)__bfloat16_as_ushort(lbb) << 16) | __bfloat16_as_ushort(lab);
    return ((uint32_t)__bfloat16_as_ushort(hb) << 16) | __bfloat16_as_ushort(ha);
}
__device__ __forceinline__ void fma4(float4& a, float s, float4 w) {
    a.x = fmaf(s, w.x, a.x); a.y = fmaf(s, w.y, a.y);
    a.z = fmaf(s, w.z, a.z); a.w = fmaf(s, w.w, a.w);
}
__device__ __forceinline__ void atomic_max_f(float* a, float v) {
    unsigned int uv = __float_as_uint(v);
    if (uv >> 31) atomicMin((unsigned int*)a, uv);
    else          atomicMax((int*)a, (int)uv);
}

// ---------------- weight prep: fp32 -> transposed bf16 hi/lo ----------------
__global__ void prep_weights(const float* __restrict__ w0, const float* __restrict__ w1,
                             const float* __restrict__ ws, const float* __restrict__ wc)
{
    int i = blockIdx.x * 256 + threadIdx.x;
    if (i < 163840) {
        int blk = i >> 15, r = i & 32767;
        int k = r >> 7, n = r & 127;
        float v0 = w0[i], vs = ws[i];
        __nv_bfloat16 h0 = __float2bfloat16(v0);
        __nv_bfloat16 hs = __float2bfloat16(vs);
        int o = (blk << 15) + n * 256 + k;
        t_w0h[o] = h0; t_w0l[o] = __float2bfloat16(v0 - __bfloat162float(h0));
        t_wsh[o] = hs; t_wsl[o] = __float2bfloat16(vs - __bfloat162float(hs));
    } else if (i < 245760) {
        int j = i - 163840;
        int blk = j >> 14, r = j & 16383;
        int k = r >> 7, n = r & 127;
        float v = w1[j];
        __nv_bfloat16 h = __float2bfloat16(v);
        int o = (blk << 14) + (n << 7) + k;
        t_w1h[o] = h; t_w1l[o] = __float2bfloat16(v - __bfloat162float(h));
    } else if (i < 262144) {
        int j = i - 245760;           // fc_c_w [128k][128n]
        int k = j >> 7, n = j & 127;
        float v = wc[j];
        __nv_bfloat16 h = __float2bfloat16(v);
        int o = (n << 7) + k;
        t_wch[o] = h; t_wcl[o] = __float2bfloat16(v - __bfloat162float(h));
    }
}

// ---------------- input: index + pos-enc + fc_pos -> g_xh/g_xl ----------------
__global__ __launch_bounds__(256) void input_kernel(
    const float* __restrict__ pg,
    const float* __restrict__ fcpw, const float* __restrict__ fcpb)
{
    extern __shared__ float sm[];
    float* peP  = sm;            // 64*64
    float* fcwc = sm + 4096;     // 20*256

    int tid = threadIdx.x;
    int pt0 = blockIdx.x * PT;

    if (tid < PT) {
        int pt = pt0 + tid;
        float px = pg[pt * 3 + 0], py = pg[pt * 3 + 1], pz = pg[pt * 3 + 2];
        const float hi = 1.0f - 1e-3f;
        float nx = fminf(fmaxf(px / 1.101f + 0.5f, 0.0f), hi);
        float ny = fminf(fmaxf(py / 1.101f + 0.5f, 0.0f), hi);
        float nz = fminf(fmaxf(pz / 1.101f + 0.5f, 0.0f), hi);
        int xi = (int)(nx * 32.0f), yi = (int)(ny * 32.0f), zi = (int)(nz * 32.0f);
        g_index[pt] = xi + 32 * (yi + 32 * zi);
    }

#pragma unroll
    for (int l = 0; l < 8; l++) {
        int task = tid + l * 256;
        if (task < PT * 30) {
            int pi = task / 30, j = task % 30;
            int fr = j / 3, coord = j % 3;
            float pv = pg[(pt0 + pi) * 3 + coord];
            float f = exp2f((float)fr) * 3.14159265358979323846f;
            float s, c;
            sincosf(f * pv, &s, &c);
            peP[pi * 64 + fr * 6 + coord]     = s;
            peP[pi * 64 + fr * 6 + 3 + coord] = c;
        }
    }

    int tc6 = tid & 63, tpg = tid >> 6;
    float4 acc[16];
#pragma unroll
    for (int p = 0; p < 16; p++) acc[p] = make_float4(0.f, 0.f, 0.f, 0.f);
    for (int kc = 0; kc < 60; kc += 20) {
        __syncthreads();
        const float4* ws = (const float4*)(fcpw + kc * 256);
#pragma unroll
        for (int l = 0; l < 5; l++) ((float4*)fcwc)[tid + l * 256] = ws[tid + l * 256];
        __syncthreads();
#pragma unroll 2
        for (int s = 0; s < 10; s++) {
            float4 w0 = ((float4*)fcwc)[(2 * s + 0) * 64 + tc6];
            float4 w1 = ((float4*)fcwc)[(2 * s + 1) * 64 + tc6];
            const float* xb = peP + (16 * tpg) * 64 + kc + 2 * s;
#pragma unroll
            for (int p = 0; p < 16; p++) {
                float2 xv = *(const float2*)(xb + p * 64);
                fma4(acc[p], xv.x, w0);
                fma4(acc[p], xv.y, w1);
            }
        }
    }
    float4 bv = *(const float4*)(fcpb + 4 * tc6);
#pragma unroll
    for (int p = 0; p < 16; p++) {
        float4 o = acc[p];
        o.x += bv.x; o.y += bv.y; o.z += bv.z; o.w += bv.w;
        uint32_t l01, l23;
        uint32_t h01 = pack_hi(o.x, o.y, l01);
        uint32_t h23 = pack_hi(o.z, o.w, l23);
        size_t base = (size_t)(pt0 + 16 * tpg + p) * 256 + 4 * tc6;
        *(uint2*)&g_xh[base] = make_uint2(h01, h23);
        *(uint2*)&g_xl[base] = make_uint2(l01, l23);
    }
}

// ---------------- HMMA tiles ----------------
// smem layout (bytes)
#define SM_AHI 0
#define SM_ALO 16384
#define SM_BHI 32768
#define SM_BLO 49152
#define SM_B0  65536
#define SM_B1  66048
#define SM_IDX 66560
#define SMEM_RBT 67072

// A loader: copy pre-split bf16 rows -> swizzled [128][64] tiles (no math)
__device__ __forceinline__ void load_a_direct(
    char* smraw, const __nv_bfloat16* __restrict__ bh,
    const __nv_bfloat16* __restrict__ bl, int stride, int tid)
{
#pragma unroll
    for (int i = 0; i < 16; i++) {
        int u = tid + i * 256;          // 0..4095
        int r = u >> 5, j2 = u & 31;
        size_t si = (size_t)r * stride + 2 * j2;
        uint32_t off = r * 128 + 4 * j2;
        uint32_t sw = off ^ ((off >> 3) & 0x70);
        *(uint32_t*)(smraw + SM_AHI + sw) = *(const uint32_t*)&bh[si];
        *(uint32_t*)(smraw + SM_ALO + sw) = *(const uint32_t*)&bl[si];
    }
}
// A loader with per-row voxel gather
__device__ __forceinline__ void load_a_gather(
    char* smraw, const __nv_bfloat16* __restrict__ bh,
    const __nv_bfloat16* __restrict__ bl, const int* idx_s, int koff, int tid)
{
#pragma unroll
    for (int i = 0; i < 16; i++) {
        int u = tid + i * 256;
        int r = u >> 5, j2 = u & 31;
        size_t si = (size_t)idx_s[r] * 128 + koff + 2 * j2;
        uint32_t off = r * 128 + 4 * j2;
        uint32_t sw = off ^ ((off >> 3) & 0x70);
        *(uint32_t*)(smraw + SM_AHI + sw) = *(const uint32_t*)&bh[si];
        *(uint32_t*)(smraw + SM_ALO + sw) = *(const uint32_t*)&bl[si];
    }
}
// B loader: [128n][64k] bf16 hi/lo tiles from [n][K] prepped weights
__device__ __forceinline__ void load_b(char* smraw, const __nv_bfloat16* wh,
                                       const __nv_bfloat16* wl, int rowStride16, int c, int tid)
{
    const uint4* wh4 = (const uint4*)wh;
    const uint4* wl4 = (const uint4*)wl;
#pragma unroll
    for (int i = 0; i < 4; i++) {
        int u = tid + i * 256;          // 0..1023
        int row = u >> 3, j = u & 7;
        uint32_t off = row * 128 + j * 16;
        uint32_t sw = off ^ ((off >> 3) & 0x70);
        *(uint4*)(smraw + SM_BHI + sw) = wh4[row * rowStride16 + c * 8 + j];
        *(uint4*)(smraw + SM_BLO + sw) = wl4[row * rowStride16 + c * 8 + j];
    }
}

// one K=64 chunk of split-bf16 MMAs; warp tile M=32 (wm), N=64 (wn)
template <bool RELU>
__device__ __forceinline__ void chunk_mma(uint32_t sb, float* d, int lane, int wm, int wn)
{
    int arow0 = wm * 32 + ((lane >> 3) & 1) * 8 + (lane & 7);
    int acol  = ((lane >> 4) & 1) * 16;
    int brow0 = wn * 64 + ((lane >> 4) & 1) * 8 + (lane & 7);
    int bcol  = ((lane >> 3) & 1) * 16;
#pragma unroll
    for (int ks = 0; ks < 4; ks++) {
        uint32_t ah[2][4], al[2][4];
#pragma unroll
        for (int mt = 0; mt < 2; mt++) {
            uint32_t off = (uint32_t)(arow0 + mt * 16) * 128 + ks * 32 + acol;
            uint32_t sw = off ^ ((off >> 3) & 0x70);
            ldsm4(ah[mt], sb + SM_AHI + sw);
            ldsm4(al[mt], sb + SM_ALO + sw);
            if (RELU) {
#pragma unroll
                for (int i = 0; i < 4; i++) {
                    uint32_t m = ((~ah[mt][i]) >> 15) & 0x00010001u;
                    m *= 0xFFFFu;
                    ah[mt][i] &= m;
                    al[mt][i] &= m;
                }
            }
        }
#pragma unroll
        for (int ntp = 0; ntp < 4; ntp++) {
            uint32_t off = (uint32_t)(brow0 + ntp * 16) * 128 + ks * 32 + bcol;
            uint32_t sw = off ^ ((off >> 3) & 0x70);
            uint32_t bh[4], bl[4];
            ldsm4(bh, sb + SM_BHI + sw);
            ldsm4(bl, sb + SM_BLO + sw);
#pragma unroll
            for (int mt = 0; mt < 2; mt++) {
                float* dp = d + (mt * 8 + ntp * 2) * 4;
                mma16816(dp, ah[mt], bh[0], bh[1]);
                mma16816(dp, al[mt], bh[0], bh[1]);
                mma16816(dp, ah[mt], bl[0], bl[1]);
                mma16816(dp + 4, ah[mt], bh[2], bh[3]);
                mma16816(dp + 4, al[mt], bh[2], bh[3]);
                mma16816(dp + 4, ah[mt], bl[2], bl[3]);
            }
        }
    }
}

__global__ __launch_bounds__(256, 2) void resblock_hmma(
    int mode, int blk, const float* __restrict__ b0g, const float* __restrict__ b1g)
{
    extern __shared__ char smraw[];
    uint32_t sb = smem_u32(smraw);
    float* bias0 = (float*)(smraw + SM_B0);
    float* bias1 = (float*)(smraw + SM_B1);
    int*   idx_s = (int*)(smraw + SM_IDX);

    int tid = threadIdx.x, lane = tid & 31, w = tid >> 5;
    int wm = w & 3, wn = w >> 2;
    int pt0 = blockIdx.x * 128;
    int b = pt0 >> 16;

    if (tid < 128) {
        bias0[tid] = b0g[tid];
        bias1[tid] = b1g[tid];
        idx_s[tid] = g_index[pt0 + tid];
    }
    __syncthreads();

    float d[64];
#pragma unroll
    for (int i = 0; i < 64; i++) d[i] = 0.f;

    // ---- pass H: D = relu(x) @ W0, K=256 ----
    for (int c = 0; c < 4; c++) {
        if (mode == 0)
            load_a_direct(smraw, g_xh + (size_t)pt0 * 256 + c * 64,
                          g_xl + (size_t)pt0 * 256 + c * 64, 256, tid);
        else if (c < 2)
            load_a_direct(smraw, g_nh + (size_t)pt0 * 128 + c * 64,
                          g_nl + (size_t)pt0 * 128 + c * 64, 128, tid);
        else
            load_a_gather(smraw, g_ph + (size_t)b * GV * 128,
                          g_pl + (size_t)b * GV * 128, idx_s, (c - 2) * 64, tid);
        load_b(smraw, t_w0h + blk * 32768, t_w0l + blk * 32768, 32, c, tid);
        __syncthreads();
        chunk_mma<true>(sb, d, lane, wm, wn);
        __syncthreads();
    }
    // h = relu(D + b0) -> g_hh/g_hl (bf16 hi/lo)
    {
        int rbase = wm * 32 + (lane >> 2);
        int cbase = wn * 64 + (lane & 3) * 2;
#pragma unroll
        for (int mt = 0; mt < 2; mt++) {
            int r0 = pt0 + rbase + mt * 16;
#pragma unroll
            for (int nt = 0; nt < 8; nt++) {
                int c0 = cbase + nt * 8;
                const float* dd = d + (mt * 8 + nt) * 4;
                float b0a = bias0[c0], b0b = bias0[c0 + 1];
                float v0 = fmaxf(dd[0] + b0a, 0.f), v1 = fmaxf(dd[1] + b0b, 0.f);
                float v2 = fmaxf(dd[2] + b0a, 0.f), v3 = fmaxf(dd[3] + b0b, 0.f);
                uint32_t l01, l23;
                uint32_t h01 = pack_hi(v0, v1, l01);
                uint32_t h23 = pack_hi(v2, v3, l23);
                *(uint32_t*)&g_hh[(size_t)r0 * 128 + c0] = h01;
                *(uint32_t*)&g_hl[(size_t)r0 * 128 + c0] = l01;
                *(uint32_t*)&g_hh[(size_t)(r0 + 8) * 128 + c0] = h23;
                *(uint32_t*)&g_hl[(size_t)(r0 + 8) * 128 + c0] = l23;
            }
        }
    }
#pragma unroll
    for (int i = 0; i < 64; i++) d[i] = 0.f;

    // ---- pass S: D = x @ Ws, K=256 ----
    for (int c = 0; c < 4; c++) {
        if (mode == 0)
            load_a_direct(smraw, g_xh + (size_t)pt0 * 256 + c * 64,
                          g_xl + (size_t)pt0 * 256 + c * 64, 256, tid);
        else if (c < 2)
            load_a_direct(smraw, g_nh + (size_t)pt0 * 128 + c * 64,
                          g_nl + (size_t)pt0 * 128 + c * 64, 128, tid);
        else
            load_a_gather(smraw, g_ph + (size_t)b * GV * 128,
                          g_pl + (size_t)b * GV * 128, idx_s, (c - 2) * 64, tid);
        load_b(smraw, t_wsh + blk * 32768, t_wsl + blk * 32768, 32, c, tid);
        __syncthreads();
        chunk_mma<false>(sb, d, lane, wm, wn);
        __syncthreads();
    }
    // ---- stage 2: D += h @ W1, K=128 ----
    for (int c = 0; c < 2; c++) {
        load_a_direct(smraw, g_hh + (size_t)pt0 * 128 + c * 64,
                      g_hl + (size_t)pt0 * 128 + c * 64, 128, tid);
        load_b(smraw, t_w1h + blk * 16384, t_w1l + blk * 16384, 16, c, tid);
        __syncthreads();
        chunk_mma<false>(sb, d, lane, wm, wn);
        __syncthreads();
    }
    // out = D + b1 -> g_nh/g_nl
    {
        int rbase = wm * 32 + (lane >> 2);
        int cbase = wn * 64 + (lane & 3) * 2;
#pragma unroll
        for (int mt = 0; mt < 2; mt++) {
            int r0 = pt0 + rbase + mt * 16;
#pragma unroll
            for (int nt = 0; nt < 8; nt++) {
                int c0 = cbase + nt * 8;
                const float* dd = d + (mt * 8 + nt) * 4;
                float b1a = bias1[c0], b1b = bias1[c0 + 1];
                uint32_t l01, l23;
                uint32_t h01 = pack_hi(dd[0] + b1a, dd[1] + b1b, l01);
                uint32_t h23 = pack_hi(dd[2] + b1a, dd[3] + b1b, l23);
                *(uint32_t*)&g_nh[(size_t)r0 * 128 + c0] = h01;
                *(uint32_t*)&g_nl[(size_t)r0 * 128 + c0] = l01;
                *(uint32_t*)&g_nh[(size_t)(r0 + 8) * 128 + c0] = h23;
                *(uint32_t*)&g_nl[(size_t)(r0 + 8) * 128 + c0] = l23;
            }
        }
    }
}

// ---------------- final fc_c HMMA + scatter add ----------------
__global__ __launch_bounds__(256, 2) void final_hmma(const float* __restrict__ bcg)
{
    extern __shared__ char smraw[];
    uint32_t sb = smem_u32(smraw);
    float* biasC = (float*)(smraw + SM_B0);
    int*   idx_s = (int*)(smraw + SM_IDX);

    int tid = threadIdx.x, lane = tid & 31, w = tid >> 5;
    int wm = w & 3, wn = w >> 2;
    int pt0 = blockIdx.x * 128;
    int b = pt0 >> 16;

    if (tid < 128) {
        biasC[tid] = bcg[tid];
        idx_s[tid] = g_index[pt0 + tid];
    }
    __syncthreads();

    float d[64];
#pragma unroll
    for (int i = 0; i < 64; i++) d[i] = 0.f;

    for (int c = 0; c < 2; c++) {
        load_a_direct(smraw, g_nh + (size_t)pt0 * 128 + c * 64,
                      g_nl + (size_t)pt0 * 128 + c * 64, 128, tid);
        load_b(smraw, t_wch, t_wcl, 16, c, tid);
        __syncthreads();
        chunk_mma<false>(sb, d, lane, wm, wn);
        __syncthreads();
    }

    int rbase = wm * 32 + (lane >> 2);
    int cbase = wn * 64 + (lane & 3) * 2;
#pragma unroll
    for (int mt = 0; mt < 2; mt++) {
        int rl = rbase + mt * 16;
        float* dst0 = &g_grid[((size_t)b * GV + idx_s[rl]) * 128];
        float* dst1 = &g_grid[((size_t)b * GV + idx_s[rl + 8]) * 128];
#pragma unroll
        for (int nt = 0; nt < 8; nt++) {
            int c0 = cbase + nt * 8;
            const float* dd = d + (mt * 8 + nt) * 4;
            float ba = biasC[c0], bb = biasC[c0 + 1];
            atomicAdd(dst0 + c0,     dd[0] + ba);
            atomicAdd(dst0 + c0 + 1, dd[1] + bb);
            atomicAdd(dst1 + c0,     dd[2] + ba);
            atomicAdd(dst1 + c0 + 1, dd[3] + bb);
        }
    }
    if (tid < 128) atomicAdd(&g_cnt[b * GV + idx_s[tid]], 1.0f);
}

// ---------------- scatter max pool: net(bf16 pair) -> grid fp32 ----------------
__global__ __launch_bounds__(256) void scatter_max_kernel()
{
    int gw = (blockIdx.x * 256 + threadIdx.x) >> 5;   // point id
    int lane = threadIdx.x & 31;
    int b = gw >> 16;
    int v = g_index[gw];
    size_t base = (size_t)gw * 128 + 4 * lane;
    __nv_bfloat162 h0 = *(const __nv_bfloat162*)&g_nh[base];
    __nv_bfloat162 h1 = *(const __nv_bfloat162*)&g_nh[base + 2];
    __nv_bfloat162 l0 = *(const __nv_bfloat162*)&g_nl[base];
    __nv_bfloat162 l1 = *(const __nv_bfloat162*)&g_nl[base + 2];
    float* dst = &g_grid[(size_t)(b * GV + v) * 128 + 4 * lane];
    atomic_max_f(dst + 0, __bfloat162float(h0.x) + __bfloat162float(l0.x));
    atomic_max_f(dst + 1, __bfloat162float(h0.y) + __bfloat162float(l0.y));
    atomic_max_f(dst + 2, __bfloat162float(h1.x) + __bfloat162float(l1.x));
    atomic_max_f(dst + 3, __bfloat162float(h1.y) + __bfloat162float(l1.y));
}

// ---------------- split pooled grid fp32 -> bf16 hi/lo ----------------
__global__ __launch_bounds__(256) void split_pool_kernel()
{
    int i = blockIdx.x * 256 + threadIdx.x;    // float2 index, total 8388608
    float2 v = ((const float2*)g_grid)[i];
    uint32_t lo;
    uint32_t hi = pack_hi(v.x, v.y, lo);
    ((uint32_t*)g_ph)[i] = hi;
    ((uint32_t*)g_pl)[i] = lo;
}

// ---------------- finalize: mean + transpose ----------------
__global__ __launch_bounds__(256) void finalize_kernel(float* __restrict__ out)
{
    __shared__ float s[32 * 129];
    __shared__ float inv[32];
    int tid = threadIdx.x;
    int blk = blockIdx.x;
    int b = blk >> 10;
    int v0 = (blk & 1023) * 32;

    const float4* src = (const float4*)&g_grid[(size_t)(b * GV + v0) * 128];
#pragma unroll
    for (int l = 0; l < 4; l++) {
        int fi = tid + l * 256;
        int vv = fi >> 5, q = fi & 31;
        float4 x = src[vv * 32 + q];
        s[vv * 129 + 4 * q + 0] = x.x;
        s[vv * 129 + 4 * q + 1] = x.y;
        s[vv * 129 + 4 * q + 2] = x.z;
        s[vv * 129 + 4 * q + 3] = x.w;
    }
    if (tid < 32) inv[tid] = 1.0f / fmaxf(g_cnt[b * GV + v0 + tid], 1.0f);
    __syncthreads();

    float* ob = out + (size_t)b * HD * GV + v0;
#pragma unroll
    for (int l = 0; l < 16; l++) {
        int oi = tid + l * 256;
        int ch = oi >> 5, vv = oi & 31;
        ob[(size_t)ch * GV + vv] = s[vv * 129 + ch] * inv[vv];
    }
}

// ---------------- fills ----------------
__global__ void fill_grid_kernel(unsigned int val)
{
    int i = blockIdx.x * 256 + threadIdx.x;
    ((uint4*)g_grid)[i] = make_uint4(val, val, val, val);
}
__global__ void fill_cnt_kernel()
{
    int i = blockIdx.x * 256 + threadIdx.x;
    if (i < NB * GV) g_cnt[i] = 0.0f;
}

// ---------------- host ----------------
extern "C" void kernel_launch(void* const* d_in, const int* in_sizes, int n_in,
                              void* d_out, int out_size)
{
    const float* p        = (const float*)d_in[0];
    const float* fc_pos_w = (const float*)d_in[1];
    const float* fc_pos_b = (const float*)d_in[2];
    const float* fc0_w    = (const float*)d_in[3];
    const float* fc0_b    = (const float*)d_in[4];
    const float* fc1_w    = (const float*)d_in[5];
    const float* fc1_b    = (const float*)d_in[6];
    const float* sc_w     = (const float*)d_in[7];
    const float* fc_c_w   = (const float*)d_in[8];
    const float* fc_c_b   = (const float*)d_in[9];
    float* out = (float*)d_out;

    const int SMEM_IN = (4096 + 5120) * 4;   // 36864

    cudaFuncSetAttribute(input_kernel,  cudaFuncAttributeMaxDynamicSharedMemorySize, SMEM_IN);
    cudaFuncSetAttribute(resblock_hmma, cudaFuncAttributeMaxDynamicSharedMemorySize, SMEM_RBT);
    cudaFuncSetAttribute(final_hmma,    cudaFuncAttributeMaxDynamicSharedMemorySize, SMEM_RBT);

    prep_weights<<<1024, 256>>>(fc0_w, fc1_w, sc_w, fc_c_w);
    input_kernel<<<NB * TPTS / PT, 256, SMEM_IN>>>(p, fc_pos_w, fc_pos_b);

    const int TNT = NB * TPTS / 128;   // 2048 tiles

    resblock_hmma<<<TNT, 256, SMEM_RBT>>>(0, 0, fc0_b, fc1_b);

    for (int i = 1; i < 5; i++) {
        fill_grid_kernel<<<16384, 256>>>(0xFFFFFFFFu);
        scatter_max_kernel<<<NB * TPTS / 8, 256>>>();
        split_pool_kernel<<<32768, 256>>>();
        resblock_hmma<<<TNT, 256, SMEM_RBT>>>(1, i, fc0_b + i * 128, fc1_b + i * 128);
    }

    fill_grid_kernel<<<16384, 256>>>(0u);
    fill_cnt_kernel<<<512, 256>>>();
    final_hmma<<<TNT, 256, SMEM_RBT>>>(fc_c_b);
    finalize_kernel<<<NB * GV / 32, 256>>>(out);
}

// round 14
// speedup vs baseline: 2.1395x; 1.1321x over previous
#include <cuda_runtime.h>
#include <cuda_bf16.h>
#include <cstdint>

// Problem constants
#define NB    4
#define TPTS  65536
#define GV    32768          // 32^3 voxels
#define HD    128
#define PT    64             // points per tile (input kernel)

// ---------------- scratch (no cudaMalloc allowed) ----------------
__device__ __align__(16) int   g_index[262144];          // [4][65536]
__device__ __align__(16) float g_grid[16777216];         // [4][32768][128] fp32 (atomics)
__device__ __align__(16) float g_cnt[131072];            // [4][32768]
__device__ __align__(16) __nv_bfloat16 g_xh[67108864];   // [4][65536][256] x hi
__device__ __align__(16) __nv_bfloat16 g_xl[67108864];   // x lo
__device__ __align__(16) __nv_bfloat16 g_nh[33554432];   // [4][65536][128] net hi
__device__ __align__(16) __nv_bfloat16 g_nl[33554432];   // net lo
__device__ __align__(16) __nv_bfloat16 g_hh[33554432];   // hidden h hi
__device__ __align__(16) __nv_bfloat16 g_hl[33554432];   // hidden h lo
__device__ __align__(16) __nv_bfloat16 g_ph[16777216];   // [4][32768][128] pooled hi
__device__ __align__(16) __nv_bfloat16 g_pl[16777216];   // pooled lo

// prepared bf16 weights, transposed to [blk][n][k], hi/lo split
__device__ __align__(16) __nv_bfloat16 t_w0h[163840], t_w0l[163840];
__device__ __align__(16) __nv_bfloat16 t_wsh[163840], t_wsl[163840];
__device__ __align__(16) __nv_bfloat16 t_w1h[81920],  t_w1l[81920];
__device__ __align__(16) __nv_bfloat16 t_wch[16384],  t_wcl[16384];

// ---------------- helpers ----------------
__device__ __forceinline__ uint32_t smem_u32(const void* p) {
    uint32_t a;
    asm("{ .reg .u64 t; cvta.to.shared.u64 t, %1; cvt.u32.u64 %0, t; }" : "=r"(a) : "l"(p));
    return a;
}
__device__ __forceinline__ void ldsm4(uint32_t r[4], uint32_t addr) {
    asm volatile("ldmatrix.sync.aligned.m8n8.x4.shared.b16 {%0,%1,%2,%3}, [%4];"
                 : "=r"(r[0]), "=r"(r[1]), "=r"(r[2]), "=r"(r[3]) : "r"(addr));
}
__device__ __forceinline__ void mma16816(float* d, const uint32_t a[4], uint32_t b0, uint32_t b1) {
    asm volatile(
        "mma.sync.aligned.m16n8k16.row.col.f32.bf16.bf16.f32 "
        "{%0,%1,%2,%3}, {%4,%5,%6,%7}, {%8,%9}, {%0,%1,%2,%3};"
        : "+f"(d[0]), "+f"(d[1]), "+f"(d[2]), "+f"(d[3])
        : "r"(a[0]), "r"(a[1]), "r"(a[2]), "r"(a[3]), "r"(b0), "r"(b1));
}
__device__ __forceinline__ void cp8(uint32_t s, const void* g) {
    asm volatile("cp.async.ca.shared.global [%0], [%1], 8;" :: "r"(s), "l"(g) : "memory");
}
__device__ __forceinline__ void cp16(uint32_t s, const void* g) {
    asm volatile("cp.async.cg.shared.global [%0], [%1], 16;" :: "r"(s), "l"(g) : "memory");
}
#define CP_COMMIT() asm volatile("cp.async.commit_group;" ::: "memory")

__device__ __forceinline__ uint32_t pack_hi(float a, float b, uint32_t& lo_out) {
    __nv_bfloat16 ha = __float2bfloat16(a);
    __nv_bfloat16 hb = __float2bfloat16(b);
    float la = a - __bfloat162float(ha);
    float lb = b - __bfloat162float(hb);
    __nv_bfloat16 lab = __float2bfloat16(la);
    __nv_bfloat16 lbb = __float2bfloat16(lb);
    lo_out = ((uint32_t)__bfloat16_as_ushort(lbb) << 16) | __bfloat16_as_ushort(lab);
    return ((uint32_t)__bfloat16_as_ushort(hb) << 16) | __bfloat16_as_ushort(ha);
}
__device__ __forceinline__ void fma4(float4& a, float s, float4 w) {
    a.x = fmaf(s, w.x, a.x); a.y = fmaf(s, w.y, a.y);
    a.z = fmaf(s, w.z, a.z); a.w = fmaf(s, w.w, a.w);
}
__device__ __forceinline__ void atomic_max_f(float* a, float v) {
    unsigned int uv = __float_as_uint(v);
    if (uv >> 31) atomicMin((unsigned int*)a, uv);
    else          atomicMax((int*)a, (int)uv);
}

// ---------------- weight prep: fp32 -> transposed bf16 hi/lo ----------------
__global__ void prep_weights(const float* __restrict__ w0, const float* __restrict__ w1,
                             const float* __restrict__ ws, const float* __restrict__ wc)
{
    int i = blockIdx.x * 256 + threadIdx.x;
    if (i < 163840) {
        int blk = i >> 15, r = i & 32767;
        int k = r >> 7, n = r & 127;
        float v0 = w0[i], vs = ws[i];
        __nv_bfloat16 h0 = __float2bfloat16(v0);
        __nv_bfloat16 hs = __float2bfloat16(vs);
        int o = (blk << 15) + n * 256 + k;
        t_w0h[o] = h0; t_w0l[o] = __float2bfloat16(v0 - __bfloat162float(h0));
        t_wsh[o] = hs; t_wsl[o] = __float2bfloat16(vs - __bfloat162float(hs));
    } else if (i < 245760) {
        int j = i - 163840;
        int blk = j >> 14, r = j & 16383;
        int k = r >> 7, n = r & 127;
        float v = w1[j];
        __nv_bfloat16 h = __float2bfloat16(v);
        int o = (blk << 14) + (n << 7) + k;
        t_w1h[o] = h; t_w1l[o] = __float2bfloat16(v - __bfloat162float(h));
    } else if (i < 262144) {
        int j = i - 245760;           // fc_c_w [128k][128n]
        int k = j >> 7, n = j & 127;
        float v = wc[j];
        __nv_bfloat16 h = __float2bfloat16(v);
        int o = (n << 7) + k;
        t_wch[o] = h; t_wcl[o] = __float2bfloat16(v - __bfloat162float(h));
    }
}

// ---------------- input: index + pos-enc + fc_pos -> g_xh/g_xl ----------------
__global__ __launch_bounds__(256) void input_kernel(
    const float* __restrict__ pg,
    const float* __restrict__ fcpw, const float* __restrict__ fcpb)
{
    extern __shared__ float sm[];
    float* peP  = sm;            // 64*64
    float* fcwc = sm + 4096;     // 20*256

    int tid = threadIdx.x;
    int pt0 = blockIdx.x * PT;

    if (tid < PT) {
        int pt = pt0 + tid;
        float px = pg[pt * 3 + 0], py = pg[pt * 3 + 1], pz = pg[pt * 3 + 2];
        const float hi = 1.0f - 1e-3f;
        float nx = fminf(fmaxf(px / 1.101f + 0.5f, 0.0f), hi);
        float ny = fminf(fmaxf(py / 1.101f + 0.5f, 0.0f), hi);
        float nz = fminf(fmaxf(pz / 1.101f + 0.5f, 0.0f), hi);
        int xi = (int)(nx * 32.0f), yi = (int)(ny * 32.0f), zi = (int)(nz * 32.0f);
        g_index[pt] = xi + 32 * (yi + 32 * zi);
    }

#pragma unroll
    for (int l = 0; l < 8; l++) {
        int task = tid + l * 256;
        if (task < PT * 30) {
            int pi = task / 30, j = task % 30;
            int fr = j / 3, coord = j % 3;
            float pv = pg[(pt0 + pi) * 3 + coord];
            float f = exp2f((float)fr) * 3.14159265358979323846f;
            float s, c;
            sincosf(f * pv, &s, &c);
            peP[pi * 64 + fr * 6 + coord]     = s;
            peP[pi * 64 + fr * 6 + 3 + coord] = c;
        }
    }

    int tc6 = tid & 63, tpg = tid >> 6;
    float4 acc[16];
#pragma unroll
    for (int p = 0; p < 16; p++) acc[p] = make_float4(0.f, 0.f, 0.f, 0.f);
    for (int kc = 0; kc < 60; kc += 20) {
        __syncthreads();
        const float4* ws = (const float4*)(fcpw + kc * 256);
#pragma unroll
        for (int l = 0; l < 5; l++) ((float4*)fcwc)[tid + l * 256] = ws[tid + l * 256];
        __syncthreads();
#pragma unroll 2
        for (int s = 0; s < 10; s++) {
            float4 w0 = ((float4*)fcwc)[(2 * s + 0) * 64 + tc6];
            float4 w1 = ((float4*)fcwc)[(2 * s + 1) * 64 + tc6];
            const float* xb = peP + (16 * tpg) * 64 + kc + 2 * s;
#pragma unroll
            for (int p = 0; p < 16; p++) {
                float2 xv = *(const float2*)(xb + p * 64);
                fma4(acc[p], xv.x, w0);
                fma4(acc[p], xv.y, w1);
            }
        }
    }
    float4 bv = *(const float4*)(fcpb + 4 * tc6);
#pragma unroll
    for (int p = 0; p < 16; p++) {
        float4 o = acc[p];
        o.x += bv.x; o.y += bv.y; o.z += bv.z; o.w += bv.w;
        uint32_t l01, l23;
        uint32_t h01 = pack_hi(o.x, o.y, l01);
        uint32_t h23 = pack_hi(o.z, o.w, l23);
        size_t base = (size_t)(pt0 + 16 * tpg + p) * 256 + 4 * tc6;
        *(uint2*)&g_xh[base] = make_uint2(h01, h23);
        *(uint2*)&g_xl[base] = make_uint2(l01, l23);
    }
}

// ================= pipelined HMMA resblock =================
// stage s (s=0,1) at byte s*32768: A tile [128r][hi 64B | lo 64B] (16KB),
// B tile at +16384 same layout. lo half addressed via (sw ^ 64) — the
// swizzle of logical offset +64 (ADD would carry into the row bits when
// the XOR key sets bit 6). misc: bias0 65536, bias1 66048, idx 66560.
#define SM_B0  65536
#define SM_B1  66048
#define SM_IDX 66560
#define SMEM_RBT 67072

// issue cp.async loads for round r (0..19) into stage (r&1)
__device__ __forceinline__ void issue_round(
    uint32_t sb, int r, int mode, int blk, const int* idx_s, int pt0, int tid)
{
    uint32_t buf = (uint32_t)(r & 1) * 32768u;
    int pass = (r < 8) ? 0 : (r < 16) ? 1 : 2;
    int c = (pass == 2) ? (r - 16) : (r & 7);

    // ---- A ----
    const __nv_bfloat16 *bh, *bl;
    int stride = 128;
    bool gather = false;
    if (pass == 2) {
        bh = g_hh + (size_t)pt0 * 128 + c * 32;
        bl = g_hl + (size_t)pt0 * 128 + c * 32;
    } else if (mode == 0) {
        bh = g_xh + (size_t)pt0 * 256 + c * 32;
        bl = g_xl + (size_t)pt0 * 256 + c * 32;
        stride = 256;
    } else if (c < 4) {
        bh = g_nh + (size_t)pt0 * 128 + c * 32;
        bl = g_nl + (size_t)pt0 * 128 + c * 32;
    } else {
        int b = pt0 >> 16;
        bh = g_ph + (size_t)b * GV * 128 + (c - 4) * 32;
        bl = g_pl + (size_t)b * GV * 128 + (c - 4) * 32;
        gather = true;
    }
#pragma unroll
    for (int i = 0; i < 4; i++) {
        int u = tid + i * 256;           // 0..1023
        int rr = u >> 3, j = u & 7;      // row, 8B unit (4 bf16)
        size_t so = gather ? (size_t)idx_s[rr] * 128 : (size_t)rr * stride;
        uint32_t off = rr * 128 + j * 8;
        uint32_t sw = off ^ ((off >> 3) & 0x70);
        cp8(sb + buf + sw,        bh + so + j * 4);
        cp8(sb + buf + (sw ^ 64), bl + so + j * 4);
    }

    // ---- B ----
    const uint4 *wh4, *wl4;
    int rs16;
    if (pass == 0)      { wh4 = (const uint4*)(t_w0h + blk * 32768); wl4 = (const uint4*)(t_w0l + blk * 32768); rs16 = 32; }
    else if (pass == 1) { wh4 = (const uint4*)(t_wsh + blk * 32768); wl4 = (const uint4*)(t_wsl + blk * 32768); rs16 = 32; }
    else                { wh4 = (const uint4*)(t_w1h + blk * 16384); wl4 = (const uint4*)(t_w1l + blk * 16384); rs16 = 16; }
#pragma unroll
    for (int i = 0; i < 2; i++) {
        int u = tid + i * 256;           // 0..511
        int row = u >> 2, j = u & 3;     // n-row, 16B unit (8 bf16)
        uint32_t off = row * 128 + j * 16;
        uint32_t sw = off ^ ((off >> 3) & 0x70);
        cp16(sb + buf + 16384 + sw,        wh4 + row * rs16 + c * 4 + j);
        cp16(sb + buf + 16384 + (sw ^ 64), wl4 + row * rs16 + c * 4 + j);
    }
}

// split-bf16 MMAs for one K=32 stage; warp tile M=32 (wm), N=64 (wn)
template <bool RELU>
__device__ __forceinline__ void chunk_mma32(uint32_t sbuf, float* d, int lane, int wm, int wn)
{
    int arow0 = wm * 32 + ((lane >> 3) & 1) * 8 + (lane & 7);
    int acol  = ((lane >> 4) & 1) * 16;
    int brow0 = wn * 64 + ((lane >> 4) & 1) * 8 + (lane & 7);
    int bcol  = ((lane >> 3) & 1) * 16;
#pragma unroll
    for (int ks = 0; ks < 2; ks++) {
        uint32_t ah[2][4], al[2][4];
#pragma unroll
        for (int mt = 0; mt < 2; mt++) {
            uint32_t off = (uint32_t)(arow0 + mt * 16) * 128 + ks * 32 + acol;
            uint32_t sw = off ^ ((off >> 3) & 0x70);
            ldsm4(ah[mt], sbuf + sw);
            ldsm4(al[mt], sbuf + (sw ^ 64));
            if (RELU) {
#pragma unroll
                for (int i = 0; i < 4; i++) {
                    uint32_t m = ((~ah[mt][i]) >> 15) & 0x00010001u;
                    m *= 0xFFFFu;
                    ah[mt][i] &= m;
                    al[mt][i] &= m;
                }
            }
        }
#pragma unroll
        for (int ntp = 0; ntp < 4; ntp++) {
            uint32_t off = (uint32_t)(brow0 + ntp * 16) * 128 + ks * 32 + bcol;
            uint32_t sw = off ^ ((off >> 3) & 0x70);
            uint32_t bh[4], bl[4];
            ldsm4(bh, sbuf + 16384 + sw);
            ldsm4(bl, sbuf + 16384 + (sw ^ 64));
#pragma unroll
            for (int mt = 0; mt < 2; mt++) {
                float* dp = d + (mt * 8 + ntp * 2) * 4;
                mma16816(dp, ah[mt], bh[0], bh[1]);
                mma16816(dp, al[mt], bh[0], bh[1]);
                mma16816(dp, ah[mt], bl[0], bl[1]);
                mma16816(dp + 4, ah[mt], bh[2], bh[3]);
                mma16816(dp + 4, al[mt], bh[2], bh[3]);
                mma16816(dp + 4, ah[mt], bl[2], bl[3]);
            }
        }
    }
}

__global__ __launch_bounds__(256, 2) void resblock_hmma(
    int mode, int blk, const float* __restrict__ b0g, const float* __restrict__ b1g)
{
    extern __shared__ char smraw[];
    uint32_t sb = smem_u32(smraw);
    float* bias0 = (float*)(smraw + SM_B0);
    float* bias1 = (float*)(smraw + SM_B1);
    int*   idx_s = (int*)(smraw + SM_IDX);

    int tid = threadIdx.x, lane = tid & 31, w = tid >> 5;
    int wm = w & 3, wn = w >> 2;
    int pt0 = blockIdx.x * 128;

    if (tid < 128) {
        bias0[tid] = b0g[tid];
        bias1[tid] = b1g[tid];
        idx_s[tid] = g_index[pt0 + tid];
    }
    __syncthreads();

    float d[64];
#pragma unroll
    for (int i = 0; i < 64; i++) d[i] = 0.f;

    issue_round(sb, 0, mode, blk, idx_s, pt0, tid); CP_COMMIT();
    issue_round(sb, 1, mode, blk, idx_s, pt0, tid); CP_COMMIT();

    for (int r = 0; r < 20; r++) {
        if (r < 19) asm volatile("cp.async.wait_group 1;" ::: "memory");
        else        asm volatile("cp.async.wait_group 0;" ::: "memory");
        __syncthreads();
        uint32_t sbuf = sb + (uint32_t)(r & 1) * 32768u;
        if (r < 8) chunk_mma32<true>(sbuf, d, lane, wm, wn);
        else       chunk_mma32<false>(sbuf, d, lane, wm, wn);

        if (r == 7) {
            // epilogue H: h = relu(D + b0) -> g_hh/g_hl; reset accumulator
            int rbase = wm * 32 + (lane >> 2);
            int cbase = wn * 64 + (lane & 3) * 2;
#pragma unroll
            for (int mt = 0; mt < 2; mt++) {
                int r0 = pt0 + rbase + mt * 16;
#pragma unroll
                for (int nt = 0; nt < 8; nt++) {
                    int c0 = cbase + nt * 8;
                    const float* dd = d + (mt * 8 + nt) * 4;
                    float b0a = bias0[c0], b0b = bias0[c0 + 1];
                    float v0 = fmaxf(dd[0] + b0a, 0.f), v1 = fmaxf(dd[1] + b0b, 0.f);
                    float v2 = fmaxf(dd[2] + b0a, 0.f), v3 = fmaxf(dd[3] + b0b, 0.f);
                    uint32_t l01, l23;
                    uint32_t h01 = pack_hi(v0, v1, l01);
                    uint32_t h23 = pack_hi(v2, v3, l23);
                    *(uint32_t*)&g_hh[(size_t)r0 * 128 + c0] = h01;
                    *(uint32_t*)&g_hl[(size_t)r0 * 128 + c0] = l01;
                    *(uint32_t*)&g_hh[(size_t)(r0 + 8) * 128 + c0] = h23;
                    *(uint32_t*)&g_hl[(size_t)(r0 + 8) * 128 + c0] = l23;
                }
            }
#pragma unroll
            for (int i = 0; i < 64; i++) d[i] = 0.f;
        }
        __syncthreads();
        if (r + 2 < 20) { issue_round(sb, r + 2, mode, blk, idx_s, pt0, tid); CP_COMMIT(); }
    }

    // out = D + b1 -> g_nh/g_nl
    {
        int rbase = wm * 32 + (lane >> 2);
        int cbase = wn * 64 + (lane & 3) * 2;
#pragma unroll
        for (int mt = 0; mt < 2; mt++) {
            int r0 = pt0 + rbase + mt * 16;
#pragma unroll
            for (int nt = 0; nt < 8; nt++) {
                int c0 = cbase + nt * 8;
                const float* dd = d + (mt * 8 + nt) * 4;
                float b1a = bias1[c0], b1b = bias1[c0 + 1];
                uint32_t l01, l23;
                uint32_t h01 = pack_hi(dd[0] + b1a, dd[1] + b1b, l01);
                uint32_t h23 = pack_hi(dd[2] + b1a, dd[3] + b1b, l23);
                *(uint32_t*)&g_nh[(size_t)r0 * 128 + c0] = h01;
                *(uint32_t*)&g_nl[(size_t)r0 * 128 + c0] = l01;
                *(uint32_t*)&g_nh[(size_t)(r0 + 8) * 128 + c0] = h23;
                *(uint32_t*)&g_nl[(size_t)(r0 + 8) * 128 + c0] = l23;
            }
        }
    }
}

// ---------------- old-layout helpers (final_hmma) ----------------
#define SM_AHI 0
#define SM_ALO 16384
#define SM_BHI 32768
#define SM_BLO 49152

__device__ __forceinline__ void load_a_direct(
    char* smraw, const __nv_bfloat16* __restrict__ bh,
    const __nv_bfloat16* __restrict__ bl, int stride, int tid)
{
#pragma unroll
    for (int i = 0; i < 16; i++) {
        int u = tid + i * 256;
        int r = u >> 5, j2 = u & 31;
        size_t si = (size_t)r * stride + 2 * j2;
        uint32_t off = r * 128 + 4 * j2;
        uint32_t sw = off ^ ((off >> 3) & 0x70);
        *(uint32_t*)(smraw + SM_AHI + sw) = *(const uint32_t*)&bh[si];
        *(uint32_t*)(smraw + SM_ALO + sw) = *(const uint32_t*)&bl[si];
    }
}
__device__ __forceinline__ void load_b(char* smraw, const __nv_bfloat16* wh,
                                       const __nv_bfloat16* wl, int rowStride16, int c, int tid)
{
    const uint4* wh4 = (const uint4*)wh;
    const uint4* wl4 = (const uint4*)wl;
#pragma unroll
    for (int i = 0; i < 4; i++) {
        int u = tid + i * 256;
        int row = u >> 3, j = u & 7;
        uint32_t off = row * 128 + j * 16;
        uint32_t sw = off ^ ((off >> 3) & 0x70);
        *(uint4*)(smraw + SM_BHI + sw) = wh4[row * rowStride16 + c * 8 + j];
        *(uint4*)(smraw + SM_BLO + sw) = wl4[row * rowStride16 + c * 8 + j];
    }
}
__device__ __forceinline__ void chunk_mma64(uint32_t sb, float* d, int lane, int wm, int wn)
{
    int arow0 = wm * 32 + ((lane >> 3) & 1) * 8 + (lane & 7);
    int acol  = ((lane >> 4) & 1) * 16;
    int brow0 = wn * 64 + ((lane >> 4) & 1) * 8 + (lane & 7);
    int bcol  = ((lane >> 3) & 1) * 16;
#pragma unroll
    for (int ks = 0; ks < 4; ks++) {
        uint32_t ah[2][4], al[2][4];
#pragma unroll
        for (int mt = 0; mt < 2; mt++) {
            uint32_t off = (uint32_t)(arow0 + mt * 16) * 128 + ks * 32 + acol;
            uint32_t sw = off ^ ((off >> 3) & 0x70);
            ldsm4(ah[mt], sb + SM_AHI + sw);
            ldsm4(al[mt], sb + SM_ALO + sw);
        }
#pragma unroll
        for (int ntp = 0; ntp < 4; ntp++) {
            uint32_t off = (uint32_t)(brow0 + ntp * 16) * 128 + ks * 32 + bcol;
            uint32_t sw = off ^ ((off >> 3) & 0x70);
            uint32_t bh[4], bl[4];
            ldsm4(bh, sb + SM_BHI + sw);
            ldsm4(bl, sb + SM_BLO + sw);
#pragma unroll
            for (int mt = 0; mt < 2; mt++) {
                float* dp = d + (mt * 8 + ntp * 2) * 4;
                mma16816(dp, ah[mt], bh[0], bh[1]);
                mma16816(dp, al[mt], bh[0], bh[1]);
                mma16816(dp, ah[mt], bl[0], bl[1]);
                mma16816(dp + 4, ah[mt], bh[2], bh[3]);
                mma16816(dp + 4, al[mt], bh[2], bh[3]);
                mma16816(dp + 4, ah[mt], bl[2], bl[3]);
            }
        }
    }
}

// ---------------- final fc_c HMMA + scatter add ----------------
__global__ __launch_bounds__(256, 2) void final_hmma(const float* __restrict__ bcg)
{
    extern __shared__ char smraw[];
    uint32_t sb = smem_u32(smraw);
    float* biasC = (float*)(smraw + SM_B0);
    int*   idx_s = (int*)(smraw + SM_IDX);

    int tid = threadIdx.x, lane = tid & 31, w = tid >> 5;
    int wm = w & 3, wn = w >> 2;
    int pt0 = blockIdx.x * 128;
    int b = pt0 >> 16;

    if (tid < 128) {
        biasC[tid] = bcg[tid];
        idx_s[tid] = g_index[pt0 + tid];
    }
    __syncthreads();

    float d[64];
#pragma unroll
    for (int i = 0; i < 64; i++) d[i] = 0.f;

    for (int c = 0; c < 2; c++) {
        load_a_direct(smraw, g_nh + (size_t)pt0 * 128 + c * 64,
                      g_nl + (size_t)pt0 * 128 + c * 64, 128, tid);
        load_b(smraw, t_wch, t_wcl, 16, c, tid);
        __syncthreads();
        chunk_mma64(sb, d, lane, wm, wn);
        __syncthreads();
    }

    int rbase = wm * 32 + (lane >> 2);
    int cbase = wn * 64 + (lane & 3) * 2;
#pragma unroll
    for (int mt = 0; mt < 2; mt++) {
        int rl = rbase + mt * 16;
        float* dst0 = &g_grid[((size_t)b * GV + idx_s[rl]) * 128];
        float* dst1 = &g_grid[((size_t)b * GV + idx_s[rl + 8]) * 128];
#pragma unroll
        for (int nt = 0; nt < 8; nt++) {
            int c0 = cbase + nt * 8;
            const float* dd = d + (mt * 8 + nt) * 4;
            float ba = biasC[c0], bb = biasC[c0 + 1];
            atomicAdd(dst0 + c0,     dd[0] + ba);
            atomicAdd(dst0 + c0 + 1, dd[1] + bb);
            atomicAdd(dst1 + c0,     dd[2] + ba);
            atomicAdd(dst1 + c0 + 1, dd[3] + bb);
        }
    }
    if (tid < 128) atomicAdd(&g_cnt[b * GV + idx_s[tid]], 1.0f);
}

// ---------------- scatter max pool: net(bf16 pair) -> grid fp32 ----------------
__global__ __launch_bounds__(256) void scatter_max_kernel()
{
    int gw = (blockIdx.x * 256 + threadIdx.x) >> 5;
    int lane = threadIdx.x & 31;
    int b = gw >> 16;
    int v = g_index[gw];
    size_t base = (size_t)gw * 128 + 4 * lane;
    __nv_bfloat162 h0 = *(const __nv_bfloat162*)&g_nh[base];
    __nv_bfloat162 h1 = *(const __nv_bfloat162*)&g_nh[base + 2];
    __nv_bfloat162 l0 = *(const __nv_bfloat162*)&g_nl[base];
    __nv_bfloat162 l1 = *(const __nv_bfloat162*)&g_nl[base + 2];
    float* dst = &g_grid[(size_t)(b * GV + v) * 128 + 4 * lane];
    atomic_max_f(dst + 0, __bfloat162float(h0.x) + __bfloat162float(l0.x));
    atomic_max_f(dst + 1, __bfloat162float(h0.y) + __bfloat162float(l0.y));
    atomic_max_f(dst + 2, __bfloat162float(h1.x) + __bfloat162float(l1.x));
    atomic_max_f(dst + 3, __bfloat162float(h1.y) + __bfloat162float(l1.y));
}

// ---------------- split pooled grid fp32 -> bf16 hi/lo ----------------
__global__ __launch_bounds__(256) void split_pool_kernel()
{
    int i = blockIdx.x * 256 + threadIdx.x;    // float2 index, total 8388608
    float2 v = ((const float2*)g_grid)[i];
    uint32_t lo;
    uint32_t hi = pack_hi(v.x, v.y, lo);
    ((uint32_t*)g_ph)[i] = hi;
    ((uint32_t*)g_pl)[i] = lo;
}

// ---------------- finalize: mean + transpose ----------------
__global__ __launch_bounds__(256) void finalize_kernel(float* __restrict__ out)
{
    __shared__ float s[32 * 129];
    __shared__ float inv[32];
    int tid = threadIdx.x;
    int blk = blockIdx.x;
    int b = blk >> 10;
    int v0 = (blk & 1023) * 32;

    const float4* src = (const float4*)&g_grid[(size_t)(b * GV + v0) * 128];
#pragma unroll
    for (int l = 0; l < 4; l++) {
        int fi = tid + l * 256;
        int vv = fi >> 5, q = fi & 31;
        float4 x = src[vv * 32 + q];
        s[vv * 129 + 4 * q + 0] = x.x;
        s[vv * 129 + 4 * q + 1] = x.y;
        s[vv * 129 + 4 * q + 2] = x.z;
        s[vv * 129 + 4 * q + 3] = x.w;
    }
    if (tid < 32) inv[tid] = 1.0f / fmaxf(g_cnt[b * GV + v0 + tid], 1.0f);
    __syncthreads();

    float* ob = out + (size_t)b * HD * GV + v0;
#pragma unroll
    for (int l = 0; l < 16; l++) {
        int oi = tid + l * 256;
        int ch = oi >> 5, vv = oi & 31;
        ob[(size_t)ch * GV + vv] = s[vv * 129 + ch] * inv[vv];
    }
}

// ---------------- fills ----------------
__global__ void fill_grid_kernel(unsigned int val)
{
    int i = blockIdx.x * 256 + threadIdx.x;
    ((uint4*)g_grid)[i] = make_uint4(val, val, val, val);
}
__global__ void fill_cnt_kernel()
{
    int i = blockIdx.x * 256 + threadIdx.x;
    if (i < NB * GV) g_cnt[i] = 0.0f;
}

// ---------------- host ----------------
extern "C" void kernel_launch(void* const* d_in, const int* in_sizes, int n_in,
                              void* d_out, int out_size)
{
    const float* p        = (const float*)d_in[0];
    const float* fc_pos_w = (const float*)d_in[1];
    const float* fc_pos_b = (const float*)d_in[2];
    const float* fc0_w    = (const float*)d_in[3];
    const float* fc0_b    = (const float*)d_in[4];
    const float* fc1_w    = (const float*)d_in[5];
    const float* fc1_b    = (const float*)d_in[6];
    const float* sc_w     = (const float*)d_in[7];
    const float* fc_c_w   = (const float*)d_in[8];
    const float* fc_c_b   = (const float*)d_in[9];
    float* out = (float*)d_out;

    const int SMEM_IN = (4096 + 5120) * 4;   // 36864

    cudaFuncSetAttribute(input_kernel,  cudaFuncAttributeMaxDynamicSharedMemorySize, SMEM_IN);
    cudaFuncSetAttribute(resblock_hmma, cudaFuncAttributeMaxDynamicSharedMemorySize, SMEM_RBT);
    cudaFuncSetAttribute(final_hmma,    cudaFuncAttributeMaxDynamicSharedMemorySize, SMEM_RBT);

    prep_weights<<<1024, 256>>>(fc0_w, fc1_w, sc_w, fc_c_w);
    input_kernel<<<NB * TPTS / PT, 256, SMEM_IN>>>(p, fc_pos_w, fc_pos_b);

    const int TNT = NB * TPTS / 128;   // 2048 tiles

    resblock_hmma<<<TNT, 256, SMEM_RBT>>>(0, 0, fc0_b, fc1_b);

    for (int i = 1; i < 5; i++) {
        fill_grid_kernel<<<16384, 256>>>(0xFFFFFFFFu);
        scatter_max_kernel<<<NB * TPTS / 8, 256>>>();
        split_pool_kernel<<<32768, 256>>>();
        resblock_hmma<<<TNT, 256, SMEM_RBT>>>(1, i, fc0_b + i * 128, fc1_b + i * 128);
    }

    fill_grid_kernel<<<16384, 256>>>(0u);
    fill_cnt_kernel<<<512, 256>>>();
    final_hmma<<<TNT, 256, SMEM_RBT>>>(fc_c_b);
    finalize_kernel<<<NB * GV / 32, 256>>>(out);
}